// round 1
// baseline (speedup 1.0000x reference)
#include <cuda_runtime.h>
#include <math.h>

// ---------------- problem constants ----------------
#define PN   2048
#define PD   1024
#define PH   16
#define PKV  4
#define PDH  64
#define PE   8
#define PF   2048
#define PCH  64
#define P_EPS 1e-6f
#define P_DT  0.1f
#define P_BASE_SCALE 10.0f

// ---------------- scratch (static device globals; no runtime alloc) ----------------
__device__ float g_hnorm[PN * PD];
__device__ float g_q[PN * PH * PDH];
__device__ float g_k[PN * PKV * PDH];
__device__ float g_v[PN * PKV * PDH];
__device__ float g_attno[PN * PH * PDH];
__device__ float g_o[PN * PD];
__device__ float g_ctrl[PN * PCH];
__device__ float g_co[PN * 3 * PD];
__device__ float g_hidmid[PN * PD];
__device__ float g_xnorm[PN * PD];
__device__ float g_G[PN * PF];
__device__ float g_U[PN * PF];
__device__ float g_mid[PN * PF];
__device__ int   g_elist[PE * PN];
__device__ int   g_ecount[PE];

// ---------------- small helpers ----------------
__device__ __forceinline__ float sigmoidf_(float x) { return 1.0f / (1.0f + expf(-x)); }
__device__ __forceinline__ float softplusf_(float x) {
    // stable: max(x,0) + log1p(exp(-|x|))
    return fmaxf(x, 0.0f) + log1pf(expf(-fabsf(x)));
}

__global__ void zero_counts_kernel() {
    int t = threadIdx.x;
    if (t < PE) g_ecount[t] = 0;
}

// ---------------- RMSNorm over D per row ----------------
__global__ void rmsnorm_kernel(const float* __restrict__ x, const float* __restrict__ w,
                               float* __restrict__ out) {
    int row = blockIdx.x;
    int tid = threadIdx.x;
    __shared__ float red[256];
    const float* xr = x + (size_t)row * PD;
    float s = 0.0f;
    for (int d = tid; d < PD; d += 256) { float v = xr[d]; s += v * v; }
    red[tid] = s; __syncthreads();
    for (int off = 128; off > 0; off >>= 1) {
        if (tid < off) red[tid] += red[tid + off];
        __syncthreads();
    }
    float scale = rsqrtf(red[0] / (float)PD + P_EPS);
    float* orow = out + (size_t)row * PD;
    for (int d = tid; d < PD; d += 256) orow[d] = xr[d] * scale * w[d];
}

// ---------------- generic guarded SGEMM 128x128x8, 256 threads, 8x8 microtile ----------------
// C[M,Nc] (+)= A[M,K] @ B[K,Nc]   (row-major, contiguous)
// flags: bit0 accumulate into C, bit1 SiLU epilogue
// gather: if non-null, A/C row index = gather[row], effective M = *countPtr
// bias: per-column add; residual: added after activation (residual[crow*Nc+col])
__global__ __launch_bounds__(256, 2)
void sgemm_kernel(const float* __restrict__ A, const float* __restrict__ B,
                  const float* __restrict__ bias,
                  const int* __restrict__ gather, const int* __restrict__ countPtr,
                  const float* __restrict__ residual,
                  float* __restrict__ C,
                  int M, int Nc, int K, int flags) {
    __shared__ float As[8][132];
    __shared__ float Bs[8][128];
    int Mreal = countPtr ? *countPtr : M;
    int m0 = blockIdx.y * 128;
    int n0 = blockIdx.x * 128;
    if (m0 >= Mreal) return;

    int tid = threadIdx.x;
    int tx = tid % 16, ty = tid / 16;
    int lkA = tid & 7, lrA = tid >> 3;          // A tile: (k, row)
    int lkB = tid >> 5, lnB = (tid & 31) * 4;   // B tile: (k, col)

    float acc[8][8];
#pragma unroll
    for (int i = 0; i < 8; i++)
#pragma unroll
        for (int j = 0; j < 8; j++) acc[i][j] = 0.0f;

    for (int k0 = 0; k0 < K; k0 += 8) {
#pragma unroll
        for (int i = 0; i < 4; i++) {
            int r = lrA + 32 * i;
            int grow = m0 + r;
            float val = 0.0f;
            if (grow < Mreal && (k0 + lkA) < K) {
                int arow = gather ? gather[grow] : grow;
                val = A[(size_t)arow * K + k0 + lkA];
            }
            As[lkA][r] = val;
        }
#pragma unroll
        for (int j = 0; j < 4; j++) {
            int col = n0 + lnB + j;
            float val = 0.0f;
            if (col < Nc && (k0 + lkB) < K) val = B[(size_t)(k0 + lkB) * Nc + col];
            Bs[lkB][lnB + j] = val;
        }
        __syncthreads();
#pragma unroll
        for (int kk = 0; kk < 8; kk++) {
            float ar[8], br[8];
#pragma unroll
            for (int i = 0; i < 4; i++) {
                ar[i]     = As[kk][ty * 4 + i];
                ar[4 + i] = As[kk][64 + ty * 4 + i];
            }
#pragma unroll
            for (int j = 0; j < 4; j++) {
                br[j]     = Bs[kk][tx * 4 + j];
                br[4 + j] = Bs[kk][64 + tx * 4 + j];
            }
#pragma unroll
            for (int i = 0; i < 8; i++)
#pragma unroll
                for (int j = 0; j < 8; j++) acc[i][j] += ar[i] * br[j];
        }
        __syncthreads();
    }

#pragma unroll
    for (int i = 0; i < 8; i++) {
        int r = (i < 4) ? (ty * 4 + i) : (64 + ty * 4 + (i - 4));
        int grow = m0 + r;
        if (grow >= Mreal) continue;
        int crow = gather ? gather[grow] : grow;
#pragma unroll
        for (int j = 0; j < 8; j++) {
            int col = n0 + ((j < 4) ? (tx * 4 + j) : (64 + tx * 4 + (j - 4)));
            if (col >= Nc) continue;
            size_t cidx = (size_t)crow * Nc + col;
            float val = acc[i][j];
            if (flags & 1) val += C[cidx];
            if (bias) val += bias[col];
            if (flags & 2) val = val / (1.0f + expf(-val));   // SiLU
            if (residual) val += residual[cidx];
            C[cidx] = val;
        }
    }
}

// ---------------- per-head RMSNorm + RoPE (warp per (n, head)) ----------------
__global__ void qknorm_rope_kernel(float* __restrict__ x, const float* __restrict__ w,
                                   const int* __restrict__ positions, int heads, int nrows) {
    int row = blockIdx.x * 8 + (threadIdx.x >> 5);
    if (row >= nrows) return;
    int lane = threadIdx.x & 31;
    int n = row / heads;
    float* base = x + (size_t)row * PDH;
    float x1 = base[lane];
    float x2 = base[lane + 32];
    float s = x1 * x1 + x2 * x2;
#pragma unroll
    for (int off = 16; off > 0; off >>= 1) s += __shfl_xor_sync(0xffffffffu, s, off);
    float scale = rsqrtf(s / (float)PDH + P_EPS);
    x1 *= scale * w[lane];
    x2 *= scale * w[lane + 32];
    // RoPE, high-precision angle
    int pos = positions[n];
    double inv = pow(10000.0, -((double)(2 * lane)) / 64.0);
    double ang = (double)pos * inv;
    float c = (float)cos(ang);
    float sn = (float)sin(ang);
    base[lane]      = x1 * c - x2 * sn;
    base[lane + 32] = x2 * c + x1 * sn;
}

// ---------------- flash attention: 64-query blocks, 32-key tiles ----------------
// grid = (N/64, H); 256 threads (ty,tx = 16x16). Non-causal full softmax.
__global__ __launch_bounds__(256)
void attn_kernel(const float* __restrict__ q, const float* __restrict__ k,
                 const float* __restrict__ v, float* __restrict__ o) {
    __shared__ float Qs[64][64];
    __shared__ float Ks[32][65];
    __shared__ float Vs[32][64];
    __shared__ float Ps[64][33];

    int qb = blockIdx.x, h = blockIdx.y;
    int kvh = h / (PH / PKV);
    int q0 = qb * 64;
    int tid = threadIdx.x;
    int tx = tid % 16, ty = tid / 16;

    for (int i = tid; i < 64 * 64; i += 256) {
        int r = i >> 6, d = i & 63;
        Qs[r][d] = q[(size_t)(q0 + r) * (PH * PDH) + h * PDH + d];
    }

    float accO[4][4];
    float m_run[4], l_run[4];
#pragma unroll
    for (int i = 0; i < 4; i++) {
        m_run[i] = -INFINITY; l_run[i] = 0.0f;
#pragma unroll
        for (int j = 0; j < 4; j++) accO[i][j] = 0.0f;
    }
    __syncthreads();

    const float scale = 0.125f;  // 1/sqrt(64)
    for (int t = 0; t < PN / 32; t++) {
        // load K, V tiles (coalesced)
        for (int i = tid; i < 32 * 64; i += 256) {
            int kk = i >> 6, d = i & 63;
            size_t gi = (size_t)(t * 32 + kk) * (PKV * PDH) + kvh * PDH + d;
            Ks[kk][d] = k[gi];
            Vs[kk][d] = v[gi];
        }
        __syncthreads();

        // S = Q K^T : frag 4x2 (rows ty*4+i, cols tx*2+j)
        float s[4][2];
#pragma unroll
        for (int i = 0; i < 4; i++) { s[i][0] = 0.0f; s[i][1] = 0.0f; }
#pragma unroll
        for (int d = 0; d < 64; d++) {
            float aq[4], bk[2];
#pragma unroll
            for (int i = 0; i < 4; i++) aq[i] = Qs[ty * 4 + i][d];
            bk[0] = Ks[tx * 2 + 0][d];
            bk[1] = Ks[tx * 2 + 1][d];
#pragma unroll
            for (int i = 0; i < 4; i++) {
                s[i][0] += aq[i] * bk[0];
                s[i][1] += aq[i] * bk[1];
            }
        }
        // online softmax update per owned row
#pragma unroll
        for (int i = 0; i < 4; i++) {
            float s0 = s[i][0] * scale, s1 = s[i][1] * scale;
            float mloc = fmaxf(s0, s1);
#pragma unroll
            for (int off = 8; off > 0; off >>= 1)
                mloc = fmaxf(mloc, __shfl_xor_sync(0xffffffffu, mloc, off));
            float mnew = fmaxf(m_run[i], mloc);
            float corr = expf(m_run[i] - mnew);   // exp(-inf)=0 on first tile
            l_run[i] *= corr;
#pragma unroll
            for (int j = 0; j < 4; j++) accO[i][j] *= corr;
            float p0 = expf(s0 - mnew), p1 = expf(s1 - mnew);
            Ps[ty * 4 + i][tx * 2 + 0] = p0;
            Ps[ty * 4 + i][tx * 2 + 1] = p1;
            float lloc = p0 + p1;
#pragma unroll
            for (int off = 8; off > 0; off >>= 1)
                lloc += __shfl_xor_sync(0xffffffffu, lloc, off);
            l_run[i] += lloc;
            m_run[i] = mnew;
        }
        __syncthreads();
        // O += P V : frag rows ty*4+i, cols tx*4+j
#pragma unroll
        for (int kk = 0; kk < 32; kk++) {
            float pv[4], vv[4];
#pragma unroll
            for (int i = 0; i < 4; i++) pv[i] = Ps[ty * 4 + i][kk];
#pragma unroll
            for (int j = 0; j < 4; j++) vv[j] = Vs[kk][tx * 4 + j];
#pragma unroll
            for (int i = 0; i < 4; i++)
#pragma unroll
                for (int j = 0; j < 4; j++) accO[i][j] += pv[i] * vv[j];
        }
        __syncthreads();
    }

#pragma unroll
    for (int i = 0; i < 4; i++) {
        float inv_l = 1.0f / l_run[i];
        int r = q0 + ty * 4 + i;
#pragma unroll
        for (int j = 0; j < 4; j++) {
            o[(size_t)r * (PH * PDH) + h * PDH + tx * 4 + j] = accO[i][j] * inv_l;
        }
    }
}

// ---------------- fused state-update elementwise ----------------
__global__ void fuse1_kernel(const float* __restrict__ co, const float* __restrict__ velocity,
                             const float* __restrict__ o, const float* __restrict__ mu_cur,
                             const float* __restrict__ hidden_in,
                             float* __restrict__ out_vnext, float* __restrict__ hidmid) {
    size_t i = (size_t)blockIdx.x * blockDim.x + threadIdx.x;
    if (i >= (size_t)PN * PD) return;
    int n = (int)(i / PD), d = (int)(i % PD);
    const float* cor = co + (size_t)n * 3 * PD;
    float alpha = sigmoidf_(cor[d]);
    float beta  = fminf(softplusf_(cor[PD + d]), 2.0f);
    float gate  = sigmoidf_(cor[2 * PD + d]);
    float ov = o[i], mc = mu_cur[i], vel = velocity[i];
    float err = ov - mc;
    float vn = alpha * vel - beta * err;
    vn = fminf(fmaxf(vn, -10.0f), 10.0f);
    out_vnext[i] = vn;
    hidmid[i] = hidden_in[i] + ov + P_DT * gate * vn;
}

// ---------------- router: warp per token ----------------
__global__ void router_kernel(const float* __restrict__ mu_cur, const float* __restrict__ w,
                              const int* __restrict__ token_ids) {
    int tkn = blockIdx.x * 8 + (threadIdx.x >> 5);
    if (tkn >= PN) return;
    int lane = threadIdx.x & 31;
    float lg[PE];
#pragma unroll
    for (int e = 0; e < PE; e++) lg[e] = 0.0f;
    const float* xr = mu_cur + (size_t)tkn * PD;
    for (int d = lane; d < PD; d += 32) {
        float xv = xr[d];
        const float* wr = w + (size_t)d * PE;
#pragma unroll
        for (int e = 0; e < PE; e++) lg[e] += xv * wr[e];
    }
#pragma unroll
    for (int e = 0; e < PE; e++) {
#pragma unroll
        for (int off = 16; off > 0; off >>= 1)
            lg[e] += __shfl_xor_sync(0xffffffffu, lg[e], off);
    }
    if (lane == 0) {
        int b = token_ids[tkn] % PE;
        lg[b] += P_BASE_SCALE;
        int best = 0; float bv = lg[0];
#pragma unroll
        for (int e = 1; e < PE; e++) {
            if (lg[e] > bv) { bv = lg[e]; best = e; }
        }
        int slot = atomicAdd(&g_ecount[best], 1);
        g_elist[best * PN + slot] = tkn;
    }
}

// ---------------- SiLU(G)*U elementwise ----------------
__global__ void midcombine_kernel() {
    size_t i = (size_t)blockIdx.x * blockDim.x + threadIdx.x;
    if (i >= (size_t)PN * PF) return;
    float gv = g_G[i];
    g_mid[i] = (gv / (1.0f + expf(-gv))) * g_U[i];
}

// ---------------- host launch ----------------
static inline void* sym_addr(const void* sym) {
    void* p = nullptr;
    cudaGetSymbolAddress(&p, sym);
    return p;
}

extern "C" void kernel_launch(void* const* d_in, const int* in_sizes, int n_in,
                              void* d_out, int out_size) {
    const float* hidden    = (const float*)d_in[0];
    const int*   positions = (const int*)d_in[1];
    const float* velocity  = (const float*)d_in[2];
    const int*   token_ids = (const int*)d_in[3];
    const float* mu_prev   = (const float*)d_in[4];
    const float* ln1_w     = (const float*)d_in[5];
    const float* ln2_w     = (const float*)d_in[6];
    const float* wq        = (const float*)d_in[7];
    const float* wk        = (const float*)d_in[8];
    const float* wv        = (const float*)d_in[9];
    const float* wo        = (const float*)d_in[10];
    const float* w_mu_q    = (const float*)d_in[11];
    const float* w_mu_k    = (const float*)d_in[12];
    const float* w_mu_v    = (const float*)d_in[13];
    const float* qnorm_w   = (const float*)d_in[14];
    const float* knorm_w   = (const float*)d_in[15];
    const float* dyn_mu    = (const float*)d_in[16];
    const float* dyn_proj  = (const float*)d_in[17];
    const float* ctrl_in_w = (const float*)d_in[18];
    const float* ctrl_in_b = (const float*)d_in[19];
    const float* ctrl_out_w= (const float*)d_in[20];
    const float* ctrl_out_b= (const float*)d_in[21];
    const float* mu_router = (const float*)d_in[22];
    const float* w_gate    = (const float*)d_in[23];
    const float* w_up      = (const float*)d_in[24];
    const float* w_down    = (const float*)d_in[25];

    float* out_hidden = (float*)d_out;
    float* out_vnext  = out_hidden + (size_t)PN * PD;
    float* out_mucur  = out_vnext  + (size_t)PN * PD;

    float* p_hnorm  = (float*)sym_addr(g_hnorm);
    float* p_q      = (float*)sym_addr(g_q);
    float* p_k      = (float*)sym_addr(g_k);
    float* p_v      = (float*)sym_addr(g_v);
    float* p_attno  = (float*)sym_addr(g_attno);
    float* p_o      = (float*)sym_addr(g_o);
    float* p_ctrl   = (float*)sym_addr(g_ctrl);
    float* p_co     = (float*)sym_addr(g_co);
    float* p_hidmid = (float*)sym_addr(g_hidmid);
    float* p_xnorm  = (float*)sym_addr(g_xnorm);
    float* p_G      = (float*)sym_addr(g_G);
    float* p_U      = (float*)sym_addr(g_U);
    float* p_mid    = (float*)sym_addr(g_mid);
    int*   p_elist  = (int*)sym_addr(g_elist);
    int*   p_ecount = (int*)sym_addr(g_ecount);

    zero_counts_kernel<<<1, 32>>>();

    // h = rmsnorm(hidden) * ln1_w
    rmsnorm_kernel<<<PN, 256>>>(hidden, ln1_w, p_hnorm);

    // q = h@wq + mu_prev@w_mu_q ; k/v analogous
    dim3 gq((PH * PDH + 127) / 128, (PN + 127) / 128);
    sgemm_kernel<<<gq, 256>>>(p_hnorm,  wq,     nullptr, nullptr, nullptr, nullptr, p_q, PN, PH * PDH, PD, 0);
    sgemm_kernel<<<gq, 256>>>(mu_prev,  w_mu_q, nullptr, nullptr, nullptr, nullptr, p_q, PN, PH * PDH, PD, 1);
    dim3 gk((PKV * PDH + 127) / 128, (PN + 127) / 128);
    sgemm_kernel<<<gk, 256>>>(p_hnorm,  wk,     nullptr, nullptr, nullptr, nullptr, p_k, PN, PKV * PDH, PD, 0);
    sgemm_kernel<<<gk, 256>>>(mu_prev,  w_mu_k, nullptr, nullptr, nullptr, nullptr, p_k, PN, PKV * PDH, PD, 1);
    sgemm_kernel<<<gk, 256>>>(p_hnorm,  wv,     nullptr, nullptr, nullptr, nullptr, p_v, PN, PKV * PDH, PD, 0);
    sgemm_kernel<<<gk, 256>>>(mu_prev,  w_mu_v, nullptr, nullptr, nullptr, nullptr, p_v, PN, PKV * PDH, PD, 1);

    // per-head rmsnorm + rope
    qknorm_rope_kernel<<<(PN * PH + 7) / 8, 256>>>(p_q, qnorm_w, positions, PH, PN * PH);
    qknorm_rope_kernel<<<(PN * PKV + 7) / 8, 256>>>(p_k, knorm_w, positions, PKV, PN * PKV);

    // attention
    attn_kernel<<<dim3(PN / 64, PH), 256>>>(p_q, p_k, p_v, p_attno);

    // o = attno @ wo
    dim3 go((PD + 127) / 128, (PN + 127) / 128);
    sgemm_kernel<<<go, 256>>>(p_attno, wo, nullptr, nullptr, nullptr, nullptr, p_o, PN, PD, PD, 0);

    // ctrl = silu([o, velocity] @ ctrl_in_w + b)
    dim3 gc((PCH + 127) / 128, (PN + 127) / 128);
    sgemm_kernel<<<gc, 256>>>(p_o,      ctrl_in_w,            nullptr,   nullptr, nullptr, nullptr, p_ctrl, PN, PCH, PD, 0);
    sgemm_kernel<<<gc, 256>>>(velocity, ctrl_in_w + PD * PCH, ctrl_in_b, nullptr, nullptr, nullptr, p_ctrl, PN, PCH, PD, 1 | 2);

    // co = ctrl @ ctrl_out_w + ctrl_out_b
    dim3 gco((3 * PD + 127) / 128, (PN + 127) / 128);
    sgemm_kernel<<<gco, 256>>>(p_ctrl, ctrl_out_w, ctrl_out_b, nullptr, nullptr, nullptr, p_co, PN, 3 * PD, PCH, 0);

    // mu_cur = dyn_mu + o @ dyn_mu_proj_w  (straight into output region)
    sgemm_kernel<<<go, 256>>>(p_o, dyn_proj, dyn_mu, nullptr, nullptr, nullptr, out_mucur, PN, PD, PD, 0);

    // state update: v_next (output), hidmid (residual2)
    fuse1_kernel<<<(PN * PD + 255) / 256, 256>>>(p_co, velocity, p_o, out_mucur, hidden,
                                                 out_vnext, p_hidmid);

    // x = rmsnorm(hidmid) * ln2_w
    rmsnorm_kernel<<<PN, 256>>>(p_hidmid, ln2_w, p_xnorm);

    // routing
    router_kernel<<<(PN + 7) / 8, 256>>>(out_mucur, mu_router, token_ids);

    // MoE stage 1: G = x@w_gate[e], U = x@w_up[e]  (gathered rows, scattered to token rows)
    dim3 gm1((PF + 127) / 128, (PN + 127) / 128);
    for (int e = 0; e < PE; e++) {
        sgemm_kernel<<<gm1, 256>>>(p_xnorm, w_gate + (size_t)e * PD * PF, nullptr,
                                   p_elist + e * PN, p_ecount + e, nullptr,
                                   p_G, PN, PF, PD, 0);
        sgemm_kernel<<<gm1, 256>>>(p_xnorm, w_up + (size_t)e * PD * PF, nullptr,
                                   p_elist + e * PN, p_ecount + e, nullptr,
                                   p_U, PN, PF, PD, 0);
    }
    midcombine_kernel<<<(PN * PF + 255) / 256, 256>>>();

    // MoE stage 2: hidden_out = hidmid + mid@w_down[e]
    dim3 gm2((PD + 127) / 128, (PN + 127) / 128);
    for (int e = 0; e < PE; e++) {
        sgemm_kernel<<<gm2, 256>>>(p_mid, w_down + (size_t)e * PF * PD, nullptr,
                                   p_elist + e * PN, p_ecount + e, p_hidmid,
                                   out_hidden, PN, PD, PF, 0);
    }
}

// round 2
// speedup vs baseline: 1.8907x; 1.8907x over previous
#include <cuda_runtime.h>
#include <math.h>
#include <stdint.h>

// ---------------- problem constants ----------------
#define PN   2048
#define PD   1024
#define PH   16
#define PKV  4
#define PDH  64
#define PE   8
#define PF   2048
#define PCH  64
#define P_EPS 1e-6f
#define P_DT  0.1f
#define P_BASE_SCALE 10.0f

// ---------------- scratch (static device globals; no runtime alloc) ----------------
__device__ float g_hnorm[PN * PD];
__device__ float g_q[PN * PH * PDH];
__device__ float g_k[PN * PKV * PDH];
__device__ float g_v[PN * PKV * PDH];
__device__ float g_attno[PN * PH * PDH];
__device__ float g_o[PN * PD];
__device__ float g_ctrl[PN * PCH];
__device__ float g_co[PN * 3 * PD];
__device__ float g_hidmid[PN * PD];
__device__ float g_xnorm[PN * PD];
__device__ float g_G[PN * PF];
__device__ float g_U[PN * PF];
__device__ float g_mid[PN * PF];
__device__ int   g_elist[PE * PN];
__device__ int   g_ecount[PE];

// ---------------- small helpers ----------------
__device__ __forceinline__ float sigmoidf_(float x) { return 1.0f / (1.0f + expf(-x)); }
__device__ __forceinline__ float softplusf_(float x) {
    return fmaxf(x, 0.0f) + log1pf(expf(-fabsf(x)));
}
__device__ __forceinline__ uint32_t f2tf32(float f) {
    uint32_t r; asm("cvt.rna.tf32.f32 %0, %1;" : "=r"(r) : "f"(f)); return r;
}
__device__ __forceinline__ void mma_tf32(float* d, const uint32_t* a, const uint32_t* b) {
    asm volatile(
        "mma.sync.aligned.m16n8k8.row.col.f32.tf32.tf32.f32 "
        "{%0,%1,%2,%3}, {%4,%5,%6,%7}, {%8,%9}, {%0,%1,%2,%3};"
        : "+f"(d[0]), "+f"(d[1]), "+f"(d[2]), "+f"(d[3])
        : "r"(a[0]), "r"(a[1]), "r"(a[2]), "r"(a[3]), "r"(b[0]), "r"(b[1]));
}

__global__ void zero_counts_kernel() {
    int t = threadIdx.x;
    if (t < PE) g_ecount[t] = 0;
}

// ---------------- RMSNorm over D per row ----------------
__global__ void rmsnorm_kernel(const float* __restrict__ x, const float* __restrict__ w,
                               float* __restrict__ out) {
    int row = blockIdx.x;
    int tid = threadIdx.x;
    __shared__ float red[256];
    const float* xr = x + (size_t)row * PD;
    float s = 0.0f;
    for (int d = tid; d < PD; d += 256) { float v = xr[d]; s += v * v; }
    red[tid] = s; __syncthreads();
    for (int off = 128; off > 0; off >>= 1) {
        if (tid < off) red[tid] += red[tid + off];
        __syncthreads();
    }
    float scale = rsqrtf(red[0] / (float)PD + P_EPS);
    float* orow = out + (size_t)row * PD;
    for (int d = tid; d < PD; d += 256) orow[d] = xr[d] * scale * w[d];
}

// ---------------- TF32 tensor-core GEMM 128x128x16, 256 threads ----------------
// C[M,Nc] (+)= A[M,K] @ B[K,Nc]   (row-major)
// flags: bit0 accumulate into C, bit1 SiLU epilogue
// gather: A/C row index = gather[pos], effective M = *countPtr
// Requirements: K % 16 == 0, Nc % 4 == 0 (cols beyond Nc zero-filled/guarded).
__global__ __launch_bounds__(256, 2)
void tf32_gemm_kernel(const float* __restrict__ A, const float* __restrict__ B,
                      const float* __restrict__ bias,
                      const int* __restrict__ gather, const int* __restrict__ countPtr,
                      const float* __restrict__ residual,
                      float* __restrict__ C,
                      int M, int Nc, int K, int flags) {
    __shared__ uint32_t As[2][128][20];   // [m][k], pad 20 -> conflict-free A frags
    __shared__ uint32_t Bs[2][16][136];   // [k][n], pad 136 -> conflict-free B frags

    int Mreal = countPtr ? *countPtr : M;
    int m0 = blockIdx.y * 128;
    int n0 = blockIdx.x * 128;
    if (m0 >= Mreal) return;

    int tid  = threadIdx.x;
    int lane = tid & 31;
    int w    = tid >> 5;
    int wm   = w >> 1;      // 0..3  (rows, 32 each)
    int wn   = w & 1;       // 0..1  (cols, 64 each)

    // A tile load mapping: 128 rows x 16 k = 512 float4; 2 per thread
    int a_r  = tid >> 2;           // 0..63 (and +64)
    int a_kq = (tid & 3) * 4;      // k quad: 0,4,8,12
    // B tile load mapping: 16 k x 128 n = 512 float4; 2 per thread
    int b_k  = tid >> 5;           // 0..7 (and +8)
    int b_nq = (tid & 31) * 4;     // n quad

    float4 aV[2], bV[2];

    float acc[2][8][4];
#pragma unroll
    for (int mf = 0; mf < 2; mf++)
#pragma unroll
        for (int nf = 0; nf < 8; nf++)
#pragma unroll
            for (int c = 0; c < 4; c++) acc[mf][nf][c] = 0.0f;

    auto loadA = [&](int k0) {
#pragma unroll
        for (int i = 0; i < 2; i++) {
            int pos = m0 + a_r + i * 64;
            if (pos < Mreal) {
                int ar = gather ? gather[pos] : pos;
                aV[i] = *reinterpret_cast<const float4*>(&A[(size_t)ar * K + k0 + a_kq]);
            } else {
                aV[i] = make_float4(0.f, 0.f, 0.f, 0.f);
            }
        }
    };
    auto loadB = [&](int k0) {
#pragma unroll
        for (int i = 0; i < 2; i++) {
            int col = n0 + b_nq;
            if (col < Nc) {
                bV[i] = *reinterpret_cast<const float4*>(&B[(size_t)(k0 + b_k + i * 8) * Nc + col]);
            } else {
                bV[i] = make_float4(0.f, 0.f, 0.f, 0.f);
            }
        }
    };
    auto stsTile = [&](int buf) {
#pragma unroll
        for (int i = 0; i < 2; i++) {
            int r = a_r + i * 64;
            As[buf][r][a_kq + 0] = f2tf32(aV[i].x);
            As[buf][r][a_kq + 1] = f2tf32(aV[i].y);
            As[buf][r][a_kq + 2] = f2tf32(aV[i].z);
            As[buf][r][a_kq + 3] = f2tf32(aV[i].w);
        }
#pragma unroll
        for (int i = 0; i < 2; i++) {
            int kr = b_k + i * 8;
            Bs[buf][kr][b_nq + 0] = f2tf32(bV[i].x);
            Bs[buf][kr][b_nq + 1] = f2tf32(bV[i].y);
            Bs[buf][kr][b_nq + 2] = f2tf32(bV[i].z);
            Bs[buf][kr][b_nq + 3] = f2tf32(bV[i].w);
        }
    };

    loadA(0); loadB(0);
    stsTile(0);
    __syncthreads();

    int buf = 0;
    for (int k0 = 16; k0 <= K; k0 += 16) {
        bool nxt = (k0 < K);
        if (nxt) { loadA(k0); loadB(k0); }

#pragma unroll
        for (int s = 0; s < 2; s++) {
            uint32_t afr[2][4], bfr[8][2];
            int kk = s * 8 + (lane & 3);
#pragma unroll
            for (int mf = 0; mf < 2; mf++) {
                int rb = wm * 32 + mf * 16 + (lane >> 2);
                afr[mf][0] = As[buf][rb][kk];
                afr[mf][1] = As[buf][rb + 8][kk];
                afr[mf][2] = As[buf][rb][kk + 4];
                afr[mf][3] = As[buf][rb + 8][kk + 4];
            }
#pragma unroll
            for (int nf = 0; nf < 8; nf++) {
                int cb = wn * 64 + nf * 8 + (lane >> 2);
                bfr[nf][0] = Bs[buf][kk][cb];
                bfr[nf][1] = Bs[buf][kk + 4][cb];
            }
#pragma unroll
            for (int mf = 0; mf < 2; mf++)
#pragma unroll
                for (int nf = 0; nf < 8; nf++)
                    mma_tf32(acc[mf][nf], afr[mf], bfr[nf]);
        }

        if (nxt) stsTile(buf ^ 1);
        __syncthreads();
        buf ^= 1;
    }

    // epilogue
#pragma unroll
    for (int mf = 0; mf < 2; mf++) {
#pragma unroll
        for (int r2 = 0; r2 < 2; r2++) {
            int pos = m0 + wm * 32 + mf * 16 + (lane >> 2) + r2 * 8;
            if (pos >= Mreal) continue;
            int crow = gather ? gather[pos] : pos;
#pragma unroll
            for (int nf = 0; nf < 8; nf++) {
#pragma unroll
                for (int c2 = 0; c2 < 2; c2++) {
                    int col = n0 + wn * 64 + nf * 8 + (lane & 3) * 2 + c2;
                    if (col >= Nc) continue;
                    size_t ci = (size_t)crow * Nc + col;
                    float val = acc[mf][nf][r2 * 2 + c2];
                    if (flags & 1) val += C[ci];
                    if (bias) val += bias[col];
                    if (flags & 2) val = val / (1.0f + expf(-val));
                    if (residual) val += residual[ci];
                    C[ci] = val;
                }
            }
        }
    }
}

// ---------------- per-head RMSNorm + RoPE (warp per (n, head)) ----------------
__global__ void qknorm_rope_kernel(float* __restrict__ x, const float* __restrict__ w,
                                   const int* __restrict__ positions, int heads, int nrows) {
    int row = blockIdx.x * 8 + (threadIdx.x >> 5);
    if (row >= nrows) return;
    int lane = threadIdx.x & 31;
    int n = row / heads;
    float* base = x + (size_t)row * PDH;
    float x1 = base[lane];
    float x2 = base[lane + 32];
    float s = x1 * x1 + x2 * x2;
#pragma unroll
    for (int off = 16; off > 0; off >>= 1) s += __shfl_xor_sync(0xffffffffu, s, off);
    float scale = rsqrtf(s / (float)PDH + P_EPS);
    x1 *= scale * w[lane];
    x2 *= scale * w[lane + 32];
    int pos = positions[n];
    double inv = pow(10000.0, -((double)(2 * lane)) / 64.0);
    double ang = (double)pos * inv;
    float c = (float)cos(ang);
    float sn = (float)sin(ang);
    base[lane]      = x1 * c - x2 * sn;
    base[lane + 32] = x2 * c + x1 * sn;
}

// ---------------- flash attention: 64-query blocks, 32-key tiles ----------------
__global__ __launch_bounds__(256)
void attn_kernel(const float* __restrict__ q, const float* __restrict__ k,
                 const float* __restrict__ v, float* __restrict__ o) {
    __shared__ float Qs[64][64];
    __shared__ float Ks[32][65];
    __shared__ float Vs[32][64];
    __shared__ float Ps[64][33];

    int qb = blockIdx.x, h = blockIdx.y;
    int kvh = h / (PH / PKV);
    int q0 = qb * 64;
    int tid = threadIdx.x;
    int tx = tid % 16, ty = tid / 16;

    for (int i = tid; i < 64 * 64; i += 256) {
        int r = i >> 6, d = i & 63;
        Qs[r][d] = q[(size_t)(q0 + r) * (PH * PDH) + h * PDH + d];
    }

    float accO[4][4];
    float m_run[4], l_run[4];
#pragma unroll
    for (int i = 0; i < 4; i++) {
        m_run[i] = -INFINITY; l_run[i] = 0.0f;
#pragma unroll
        for (int j = 0; j < 4; j++) accO[i][j] = 0.0f;
    }
    __syncthreads();

    const float scale = 0.125f;
    for (int t = 0; t < PN / 32; t++) {
        for (int i = tid; i < 32 * 64; i += 256) {
            int kk = i >> 6, d = i & 63;
            size_t gi = (size_t)(t * 32 + kk) * (PKV * PDH) + kvh * PDH + d;
            Ks[kk][d] = k[gi];
            Vs[kk][d] = v[gi];
        }
        __syncthreads();

        float s[4][2];
#pragma unroll
        for (int i = 0; i < 4; i++) { s[i][0] = 0.0f; s[i][1] = 0.0f; }
#pragma unroll
        for (int d = 0; d < 64; d++) {
            float aq[4], bk[2];
#pragma unroll
            for (int i = 0; i < 4; i++) aq[i] = Qs[ty * 4 + i][d];
            bk[0] = Ks[tx * 2 + 0][d];
            bk[1] = Ks[tx * 2 + 1][d];
#pragma unroll
            for (int i = 0; i < 4; i++) {
                s[i][0] += aq[i] * bk[0];
                s[i][1] += aq[i] * bk[1];
            }
        }
#pragma unroll
        for (int i = 0; i < 4; i++) {
            float s0 = s[i][0] * scale, s1 = s[i][1] * scale;
            float mloc = fmaxf(s0, s1);
#pragma unroll
            for (int off = 8; off > 0; off >>= 1)
                mloc = fmaxf(mloc, __shfl_xor_sync(0xffffffffu, mloc, off));
            float mnew = fmaxf(m_run[i], mloc);
            float corr = expf(m_run[i] - mnew);
            l_run[i] *= corr;
#pragma unroll
            for (int j = 0; j < 4; j++) accO[i][j] *= corr;
            float p0 = expf(s0 - mnew), p1 = expf(s1 - mnew);
            Ps[ty * 4 + i][tx * 2 + 0] = p0;
            Ps[ty * 4 + i][tx * 2 + 1] = p1;
            float lloc = p0 + p1;
#pragma unroll
            for (int off = 8; off > 0; off >>= 1)
                lloc += __shfl_xor_sync(0xffffffffu, lloc, off);
            l_run[i] += lloc;
            m_run[i] = mnew;
        }
        __syncthreads();
#pragma unroll
        for (int kk = 0; kk < 32; kk++) {
            float pv[4], vv[4];
#pragma unroll
            for (int i = 0; i < 4; i++) pv[i] = Ps[ty * 4 + i][kk];
#pragma unroll
            for (int j = 0; j < 4; j++) vv[j] = Vs[kk][tx * 4 + j];
#pragma unroll
            for (int i = 0; i < 4; i++)
#pragma unroll
                for (int j = 0; j < 4; j++) accO[i][j] += pv[i] * vv[j];
        }
        __syncthreads();
    }

#pragma unroll
    for (int i = 0; i < 4; i++) {
        float inv_l = 1.0f / l_run[i];
        int r = q0 + ty * 4 + i;
#pragma unroll
        for (int j = 0; j < 4; j++) {
            o[(size_t)r * (PH * PDH) + h * PDH + tx * 4 + j] = accO[i][j] * inv_l;
        }
    }
}

// ---------------- fused state-update elementwise ----------------
__global__ void fuse1_kernel(const float* __restrict__ co, const float* __restrict__ velocity,
                             const float* __restrict__ o, const float* __restrict__ mu_cur,
                             const float* __restrict__ hidden_in,
                             float* __restrict__ out_vnext, float* __restrict__ hidmid) {
    size_t i = (size_t)blockIdx.x * blockDim.x + threadIdx.x;
    if (i >= (size_t)PN * PD) return;
    int n = (int)(i / PD), d = (int)(i % PD);
    const float* cor = co + (size_t)n * 3 * PD;
    float alpha = sigmoidf_(cor[d]);
    float beta  = fminf(softplusf_(cor[PD + d]), 2.0f);
    float gate  = sigmoidf_(cor[2 * PD + d]);
    float ov = o[i], mc = mu_cur[i], vel = velocity[i];
    float err = ov - mc;
    float vn = alpha * vel - beta * err;
    vn = fminf(fmaxf(vn, -10.0f), 10.0f);
    out_vnext[i] = vn;
    hidmid[i] = hidden_in[i] + ov + P_DT * gate * vn;
}

// ---------------- router: warp per token ----------------
__global__ void router_kernel(const float* __restrict__ mu_cur, const float* __restrict__ w,
                              const int* __restrict__ token_ids) {
    int tkn = blockIdx.x * 8 + (threadIdx.x >> 5);
    if (tkn >= PN) return;
    int lane = threadIdx.x & 31;
    float lg[PE];
#pragma unroll
    for (int e = 0; e < PE; e++) lg[e] = 0.0f;
    const float* xr = mu_cur + (size_t)tkn * PD;
    for (int d = lane; d < PD; d += 32) {
        float xv = xr[d];
        const float* wr = w + (size_t)d * PE;
#pragma unroll
        for (int e = 0; e < PE; e++) lg[e] += xv * wr[e];
    }
#pragma unroll
    for (int e = 0; e < PE; e++) {
#pragma unroll
        for (int off = 16; off > 0; off >>= 1)
            lg[e] += __shfl_xor_sync(0xffffffffu, lg[e], off);
    }
    if (lane == 0) {
        int b = token_ids[tkn] % PE;
        lg[b] += P_BASE_SCALE;
        int best = 0; float bv = lg[0];
#pragma unroll
        for (int e = 1; e < PE; e++) {
            if (lg[e] > bv) { bv = lg[e]; best = e; }
        }
        int slot = atomicAdd(&g_ecount[best], 1);
        g_elist[best * PN + slot] = tkn;
    }
}

// ---------------- SiLU(G)*U elementwise ----------------
__global__ void midcombine_kernel() {
    size_t i = (size_t)blockIdx.x * blockDim.x + threadIdx.x;
    if (i >= (size_t)PN * PF) return;
    float gv = g_G[i];
    g_mid[i] = (gv / (1.0f + expf(-gv))) * g_U[i];
}

// ---------------- host launch ----------------
static inline void* sym_addr(const void* sym) {
    void* p = nullptr;
    cudaGetSymbolAddress(&p, sym);
    return p;
}

extern "C" void kernel_launch(void* const* d_in, const int* in_sizes, int n_in,
                              void* d_out, int out_size) {
    const float* hidden    = (const float*)d_in[0];
    const int*   positions = (const int*)d_in[1];
    const float* velocity  = (const float*)d_in[2];
    const int*   token_ids = (const int*)d_in[3];
    const float* mu_prev   = (const float*)d_in[4];
    const float* ln1_w     = (const float*)d_in[5];
    const float* ln2_w     = (const float*)d_in[6];
    const float* wq        = (const float*)d_in[7];
    const float* wk        = (const float*)d_in[8];
    const float* wv        = (const float*)d_in[9];
    const float* wo        = (const float*)d_in[10];
    const float* w_mu_q    = (const float*)d_in[11];
    const float* w_mu_k    = (const float*)d_in[12];
    const float* w_mu_v    = (const float*)d_in[13];
    const float* qnorm_w   = (const float*)d_in[14];
    const float* knorm_w   = (const float*)d_in[15];
    const float* dyn_mu    = (const float*)d_in[16];
    const float* dyn_proj  = (const float*)d_in[17];
    const float* ctrl_in_w = (const float*)d_in[18];
    const float* ctrl_in_b = (const float*)d_in[19];
    const float* ctrl_out_w= (const float*)d_in[20];
    const float* ctrl_out_b= (const float*)d_in[21];
    const float* mu_router = (const float*)d_in[22];
    const float* w_gate    = (const float*)d_in[23];
    const float* w_up      = (const float*)d_in[24];
    const float* w_down    = (const float*)d_in[25];

    float* out_hidden = (float*)d_out;
    float* out_vnext  = out_hidden + (size_t)PN * PD;
    float* out_mucur  = out_vnext  + (size_t)PN * PD;

    float* p_hnorm  = (float*)sym_addr(g_hnorm);
    float* p_q      = (float*)sym_addr(g_q);
    float* p_k      = (float*)sym_addr(g_k);
    float* p_v      = (float*)sym_addr(g_v);
    float* p_attno  = (float*)sym_addr(g_attno);
    float* p_o      = (float*)sym_addr(g_o);
    float* p_ctrl   = (float*)sym_addr(g_ctrl);
    float* p_co     = (float*)sym_addr(g_co);
    float* p_hidmid = (float*)sym_addr(g_hidmid);
    float* p_xnorm  = (float*)sym_addr(g_xnorm);
    float* p_G      = (float*)sym_addr(g_G);
    float* p_U      = (float*)sym_addr(g_U);
    float* p_mid    = (float*)sym_addr(g_mid);
    int*   p_elist  = (int*)sym_addr(g_elist);
    int*   p_ecount = (int*)sym_addr(g_ecount);

    zero_counts_kernel<<<1, 32>>>();
    rmsnorm_kernel<<<PN, 256>>>(hidden, ln1_w, p_hnorm);

    // q = h@wq + mu_prev@w_mu_q ; k/v analogous  (all tf32 tensor-core)
    dim3 gq((PH * PDH + 127) / 128, (PN + 127) / 128);
    tf32_gemm_kernel<<<gq, 256>>>(p_hnorm,  wq,     nullptr, nullptr, nullptr, nullptr, p_q, PN, PH * PDH, PD, 0);
    tf32_gemm_kernel<<<gq, 256>>>(mu_prev,  w_mu_q, nullptr, nullptr, nullptr, nullptr, p_q, PN, PH * PDH, PD, 1);
    dim3 gk((PKV * PDH + 127) / 128, (PN + 127) / 128);
    tf32_gemm_kernel<<<gk, 256>>>(p_hnorm,  wk,     nullptr, nullptr, nullptr, nullptr, p_k, PN, PKV * PDH, PD, 0);
    tf32_gemm_kernel<<<gk, 256>>>(mu_prev,  w_mu_k, nullptr, nullptr, nullptr, nullptr, p_k, PN, PKV * PDH, PD, 1);
    tf32_gemm_kernel<<<gk, 256>>>(p_hnorm,  wv,     nullptr, nullptr, nullptr, nullptr, p_v, PN, PKV * PDH, PD, 0);
    tf32_gemm_kernel<<<gk, 256>>>(mu_prev,  w_mu_v, nullptr, nullptr, nullptr, nullptr, p_v, PN, PKV * PDH, PD, 1);

    qknorm_rope_kernel<<<(PN * PH + 7) / 8, 256>>>(p_q, qnorm_w, positions, PH, PN * PH);
    qknorm_rope_kernel<<<(PN * PKV + 7) / 8, 256>>>(p_k, knorm_w, positions, PKV, PN * PKV);

    attn_kernel<<<dim3(PN / 64, PH), 256>>>(p_q, p_k, p_v, p_attno);

    // o = attno @ wo
    dim3 go((PD + 127) / 128, (PN + 127) / 128);
    tf32_gemm_kernel<<<go, 256>>>(p_attno, wo, nullptr, nullptr, nullptr, nullptr, p_o, PN, PD, PD, 0);

    // ctrl = silu([o, velocity] @ ctrl_in_w + b)
    dim3 gc(1, (PN + 127) / 128);
    tf32_gemm_kernel<<<gc, 256>>>(p_o,      ctrl_in_w,            nullptr,   nullptr, nullptr, nullptr, p_ctrl, PN, PCH, PD, 0);
    tf32_gemm_kernel<<<gc, 256>>>(velocity, ctrl_in_w + PD * PCH, ctrl_in_b, nullptr, nullptr, nullptr, p_ctrl, PN, PCH, PD, 1 | 2);

    // co = ctrl @ ctrl_out_w + ctrl_out_b
    dim3 gco((3 * PD + 127) / 128, (PN + 127) / 128);
    tf32_gemm_kernel<<<gco, 256>>>(p_ctrl, ctrl_out_w, ctrl_out_b, nullptr, nullptr, nullptr, p_co, PN, 3 * PD, PCH, 0);

    // mu_cur = dyn_mu + o @ dyn_mu_proj_w
    tf32_gemm_kernel<<<go, 256>>>(p_o, dyn_proj, dyn_mu, nullptr, nullptr, nullptr, out_mucur, PN, PD, PD, 0);

    fuse1_kernel<<<(PN * PD + 255) / 256, 256>>>(p_co, velocity, p_o, out_mucur, hidden,
                                                 out_vnext, p_hidmid);

    rmsnorm_kernel<<<PN, 256>>>(p_hidmid, ln2_w, p_xnorm);
    router_kernel<<<(PN + 7) / 8, 256>>>(out_mucur, mu_router, token_ids);

    // MoE stage 1: G = x@w_gate[e], U = x@w_up[e]
    dim3 gm1((PF + 127) / 128, (PN + 127) / 128);
    for (int e = 0; e < PE; e++) {
        tf32_gemm_kernel<<<gm1, 256>>>(p_xnorm, w_gate + (size_t)e * PD * PF, nullptr,
                                       p_elist + e * PN, p_ecount + e, nullptr,
                                       p_G, PN, PF, PD, 0);
        tf32_gemm_kernel<<<gm1, 256>>>(p_xnorm, w_up + (size_t)e * PD * PF, nullptr,
                                       p_elist + e * PN, p_ecount + e, nullptr,
                                       p_U, PN, PF, PD, 0);
    }
    midcombine_kernel<<<(PN * PF + 255) / 256, 256>>>();

    // MoE stage 2: hidden_out = hidmid + mid@w_down[e]
    dim3 gm2((PD + 127) / 128, (PN + 127) / 128);
    for (int e = 0; e < PE; e++) {
        tf32_gemm_kernel<<<gm2, 256>>>(p_mid, w_down + (size_t)e * PF * PD, nullptr,
                                       p_elist + e * PN, p_ecount + e, p_hidmid,
                                       out_hidden, PN, PD, PF, 0);
    }
}

// round 3
// speedup vs baseline: 3.0520x; 1.6142x over previous
#include <cuda_runtime.h>
#include <math.h>
#include <stdint.h>

// ---------------- problem constants ----------------
#define PN   2048
#define PD   1024
#define PH   16
#define PKV  4
#define PDH  64
#define PE   8
#define PF   2048
#define PCH  64
#define P_EPS 1e-6f
#define P_DT  0.1f
#define P_BASE_SCALE 10.0f

// ---------------- scratch (static device globals; no runtime alloc) ----------------
__device__ float g_hnorm[PN * PD];
__device__ float g_q[PN * PH * PDH];
__device__ float g_k[PN * PKV * PDH];
__device__ float g_v[PN * PKV * PDH];
__device__ float g_attno[PN * PH * PDH];
__device__ float g_o[PN * PD];
__device__ float g_ctrl[PN * PCH];
__device__ float g_co[PN * 3 * PD];
__device__ float g_hidmid[PN * PD];
__device__ float g_xnorm[PN * PD];
__device__ float g_G[PN * PF];
__device__ float g_U[PN * PF];
__device__ float g_mid[PN * PF];
__device__ float g_cosT[PN * 32];
__device__ float g_sinT[PN * 32];
__device__ int   g_elist[PE * PN];
__device__ int   g_ecount[PE];

// ---------------- small helpers ----------------
__device__ __forceinline__ float sigmoidf_(float x) { return 1.0f / (1.0f + expf(-x)); }
__device__ __forceinline__ float softplusf_(float x) {
    return fmaxf(x, 0.0f) + log1pf(expf(-fabsf(x)));
}
__device__ __forceinline__ uint32_t f2tf32(float f) {
    uint32_t r; asm("cvt.rna.tf32.f32 %0, %1;" : "=r"(r) : "f"(f)); return r;
}
__device__ __forceinline__ void mma_tf32(float* d, const uint32_t* a, const uint32_t* b) {
    asm volatile(
        "mma.sync.aligned.m16n8k8.row.col.f32.tf32.tf32.f32 "
        "{%0,%1,%2,%3}, {%4,%5,%6,%7}, {%8,%9}, {%0,%1,%2,%3};"
        : "+f"(d[0]), "+f"(d[1]), "+f"(d[2]), "+f"(d[3])
        : "r"(a[0]), "r"(a[1]), "r"(a[2]), "r"(a[3]), "r"(b[0]), "r"(b[1]));
}

__global__ void zero_counts_kernel() {
    int t = threadIdx.x;
    if (t < PE) g_ecount[t] = 0;
}

// ---------------- RoPE table build (double pow only 32x per block) ----------------
__global__ void rope_table_kernel(const int* __restrict__ positions) {
    __shared__ float sm_inv[32];
    if (threadIdx.x < 32) {
        double inv = pow(10000.0, -((double)(2 * threadIdx.x)) / 64.0);
        sm_inv[threadIdx.x] = (float)inv;
    }
    __syncthreads();
    int i = blockIdx.x * 256 + threadIdx.x;
    if (i >= PN * 32) return;
    int n = i >> 5, f = i & 31;
    float ang = (float)positions[n] * sm_inv[f];
    float s, c;
    sincosf(ang, &s, &c);
    g_cosT[i] = c;
    g_sinT[i] = s;
}

// ---------------- RMSNorm over D per row ----------------
__global__ void rmsnorm_kernel(const float* __restrict__ x, const float* __restrict__ w,
                               float* __restrict__ out) {
    int row = blockIdx.x;
    int tid = threadIdx.x;
    __shared__ float red[256];
    const float* xr = x + (size_t)row * PD;
    float s = 0.0f;
    for (int d = tid; d < PD; d += 256) { float v = xr[d]; s += v * v; }
    red[tid] = s; __syncthreads();
    for (int off = 128; off > 0; off >>= 1) {
        if (tid < off) red[tid] += red[tid + off];
        __syncthreads();
    }
    float scale = rsqrtf(red[0] / (float)PD + P_EPS);
    float* orow = out + (size_t)row * PD;
    for (int d = tid; d < PD; d += 256) orow[d] = xr[d] * scale * w[d];
}

// ---------------- TF32 tensor-core GEMM 128x128x16, 256 threads, dual-input concat-K ----------------
// C[M,Nc] = (A[M,K1] @ B[K1,Nc]) (+ A2[M,K-K1] @ B2[K-K1,Nc] if A2) + bias, epilogues
// flags: bit1 SiLU epilogue. gather: A/C row = gather[pos], M = *countPtr.
__global__ __launch_bounds__(256, 2)
void tf32_gemm_kernel(const float* __restrict__ A, const float* __restrict__ B,
                      const float* __restrict__ A2, const float* __restrict__ B2,
                      const float* __restrict__ bias,
                      const int* __restrict__ gather, const int* __restrict__ countPtr,
                      const float* __restrict__ residual,
                      float* __restrict__ C,
                      int M, int Nc, int K, int K1, int flags) {
    __shared__ uint32_t As[2][128][20];
    __shared__ uint32_t Bs[2][16][136];

    int Mreal = countPtr ? *countPtr : M;
    int m0 = blockIdx.y * 128;
    int n0 = blockIdx.x * 128;
    if (m0 >= Mreal) return;

    int tid  = threadIdx.x;
    int lane = tid & 31;
    int w    = tid >> 5;
    int wm   = w >> 1;
    int wn   = w & 1;

    int a_r  = tid >> 2;
    int a_kq = (tid & 3) * 4;
    int b_k  = tid >> 5;
    int b_nq = (tid & 31) * 4;

    float4 aV[2], bV[2];

    float acc[2][8][4];
#pragma unroll
    for (int mf = 0; mf < 2; mf++)
#pragma unroll
        for (int nf = 0; nf < 8; nf++)
#pragma unroll
            for (int c = 0; c < 4; c++) acc[mf][nf][c] = 0.0f;

    auto loadA = [&](int k0) {
        const float* Ap = A; int lda = K1; int kk = k0;
        if (k0 >= K1) { Ap = A2; lda = K - K1; kk = k0 - K1; }
#pragma unroll
        for (int i = 0; i < 2; i++) {
            int pos = m0 + a_r + i * 64;
            if (pos < Mreal) {
                int ar = gather ? gather[pos] : pos;
                aV[i] = *reinterpret_cast<const float4*>(&Ap[(size_t)ar * lda + kk + a_kq]);
            } else {
                aV[i] = make_float4(0.f, 0.f, 0.f, 0.f);
            }
        }
    };
    auto loadB = [&](int k0) {
        const float* Bp = B; int kk = k0;
        if (k0 >= K1) { Bp = B2; kk = k0 - K1; }
#pragma unroll
        for (int i = 0; i < 2; i++) {
            int col = n0 + b_nq;
            if (col < Nc) {
                bV[i] = *reinterpret_cast<const float4*>(&Bp[(size_t)(kk + b_k + i * 8) * Nc + col]);
            } else {
                bV[i] = make_float4(0.f, 0.f, 0.f, 0.f);
            }
        }
    };
    auto stsTile = [&](int buf) {
#pragma unroll
        for (int i = 0; i < 2; i++) {
            int r = a_r + i * 64;
            As[buf][r][a_kq + 0] = f2tf32(aV[i].x);
            As[buf][r][a_kq + 1] = f2tf32(aV[i].y);
            As[buf][r][a_kq + 2] = f2tf32(aV[i].z);
            As[buf][r][a_kq + 3] = f2tf32(aV[i].w);
        }
#pragma unroll
        for (int i = 0; i < 2; i++) {
            int kr = b_k + i * 8;
            Bs[buf][kr][b_nq + 0] = f2tf32(bV[i].x);
            Bs[buf][kr][b_nq + 1] = f2tf32(bV[i].y);
            Bs[buf][kr][b_nq + 2] = f2tf32(bV[i].z);
            Bs[buf][kr][b_nq + 3] = f2tf32(bV[i].w);
        }
    };

    loadA(0); loadB(0);
    stsTile(0);
    __syncthreads();

    int buf = 0;
    for (int k0 = 16; k0 <= K; k0 += 16) {
        bool nxt = (k0 < K);
        if (nxt) { loadA(k0); loadB(k0); }

#pragma unroll
        for (int s = 0; s < 2; s++) {
            uint32_t afr[2][4], bfr[8][2];
            int kk = s * 8 + (lane & 3);
#pragma unroll
            for (int mf = 0; mf < 2; mf++) {
                int rb = wm * 32 + mf * 16 + (lane >> 2);
                afr[mf][0] = As[buf][rb][kk];
                afr[mf][1] = As[buf][rb + 8][kk];
                afr[mf][2] = As[buf][rb][kk + 4];
                afr[mf][3] = As[buf][rb + 8][kk + 4];
            }
#pragma unroll
            for (int nf = 0; nf < 8; nf++) {
                int cb = wn * 64 + nf * 8 + (lane >> 2);
                bfr[nf][0] = Bs[buf][kk][cb];
                bfr[nf][1] = Bs[buf][kk + 4][cb];
            }
#pragma unroll
            for (int mf = 0; mf < 2; mf++)
#pragma unroll
                for (int nf = 0; nf < 8; nf++)
                    mma_tf32(acc[mf][nf], afr[mf], bfr[nf]);
        }

        if (nxt) stsTile(buf ^ 1);
        __syncthreads();
        buf ^= 1;
    }

#pragma unroll
    for (int mf = 0; mf < 2; mf++) {
#pragma unroll
        for (int r2 = 0; r2 < 2; r2++) {
            int pos = m0 + wm * 32 + mf * 16 + (lane >> 2) + r2 * 8;
            if (pos >= Mreal) continue;
            int crow = gather ? gather[pos] : pos;
#pragma unroll
            for (int nf = 0; nf < 8; nf++) {
#pragma unroll
                for (int c2 = 0; c2 < 2; c2++) {
                    int col = n0 + wn * 64 + nf * 8 + (lane & 3) * 2 + c2;
                    if (col >= Nc) continue;
                    size_t ci = (size_t)crow * Nc + col;
                    float val = acc[mf][nf][r2 * 2 + c2];
                    if (bias) val += bias[col];
                    if (flags & 2) val = val / (1.0f + expf(-val));
                    if (residual) val += residual[ci];
                    C[ci] = val;
                }
            }
        }
    }
}

// ---------------- per-head RMSNorm + RoPE (warp per (n, head)), table-based ----------------
__global__ void qknorm_rope_kernel(float* __restrict__ x, const float* __restrict__ w,
                                   int heads, int nrows) {
    int row = blockIdx.x * 8 + (threadIdx.x >> 5);
    if (row >= nrows) return;
    int lane = threadIdx.x & 31;
    int n = row / heads;
    float* base = x + (size_t)row * PDH;
    float x1 = base[lane];
    float x2 = base[lane + 32];
    float s = x1 * x1 + x2 * x2;
#pragma unroll
    for (int off = 16; off > 0; off >>= 1) s += __shfl_xor_sync(0xffffffffu, s, off);
    float scale = rsqrtf(s / (float)PDH + P_EPS);
    x1 *= scale * w[lane];
    x2 *= scale * w[lane + 32];
    float c  = g_cosT[n * 32 + lane];
    float sn = g_sinT[n * 32 + lane];
    base[lane]      = x1 * c - x2 * sn;
    base[lane + 32] = x2 * c + x1 * sn;
}

// ---------------- flash attention: 64-query blocks, 32-key tiles, vectorized ----------------
__global__ __launch_bounds__(256, 2)
void attn_kernel(const float* __restrict__ q, const float* __restrict__ k,
                 const float* __restrict__ v, float* __restrict__ o) {
    __shared__ float Qs[64][64];
    __shared__ float Ks[32][65];
    __shared__ float Vs[32][64];
    __shared__ float Ps[64][33];

    int qb = blockIdx.x, h = blockIdx.y;
    int kvh = h / (PH / PKV);
    int q0 = qb * 64;
    int tid = threadIdx.x;
    int tx = tid % 16, ty = tid / 16;

    // load Q (float4)
    for (int i = tid; i < 64 * 16; i += 256) {
        int r = i >> 4, d4 = (i & 15) * 4;
        *reinterpret_cast<float4*>(&Qs[r][d4]) =
            *reinterpret_cast<const float4*>(&q[(size_t)(q0 + r) * (PH * PDH) + h * PDH + d4]);
    }

    float accO[4][4];
    float m_run[4], l_run[4];
#pragma unroll
    for (int i = 0; i < 4; i++) {
        m_run[i] = -INFINITY; l_run[i] = 0.0f;
#pragma unroll
        for (int j = 0; j < 4; j++) accO[i][j] = 0.0f;
    }
    __syncthreads();

    const float scale = 0.125f;
    for (int t = 0; t < PN / 32; t++) {
        for (int i = tid; i < 32 * 16; i += 256) {
            int r = i >> 4, d4 = (i & 15) * 4;
            size_t gi = (size_t)(t * 32 + r) * (PKV * PDH) + kvh * PDH + d4;
            float4 kv = *reinterpret_cast<const float4*>(&k[gi]);
            Ks[r][d4 + 0] = kv.x; Ks[r][d4 + 1] = kv.y;
            Ks[r][d4 + 2] = kv.z; Ks[r][d4 + 3] = kv.w;
            *reinterpret_cast<float4*>(&Vs[r][d4]) = *reinterpret_cast<const float4*>(&v[gi]);
        }
        __syncthreads();

        // S = Q K^T : rows ty*4+i, cols tx*2+j
        float s[4][2];
#pragma unroll
        for (int i = 0; i < 4; i++) { s[i][0] = 0.0f; s[i][1] = 0.0f; }
#pragma unroll
        for (int d4 = 0; d4 < 16; d4++) {
            float4 aq[4];
#pragma unroll
            for (int i = 0; i < 4; i++)
                aq[i] = *reinterpret_cast<const float4*>(&Qs[ty * 4 + i][d4 * 4]);
#pragma unroll
            for (int j = 0; j < 2; j++) {
                int kr = tx * 2 + j;
                float b0 = Ks[kr][d4 * 4 + 0], b1 = Ks[kr][d4 * 4 + 1];
                float b2 = Ks[kr][d4 * 4 + 2], b3 = Ks[kr][d4 * 4 + 3];
#pragma unroll
                for (int i = 0; i < 4; i++) {
                    s[i][j] += aq[i].x * b0 + aq[i].y * b1 + aq[i].z * b2 + aq[i].w * b3;
                }
            }
        }
        // online softmax (reduce across 16 tx lanes: offsets 8..1)
#pragma unroll
        for (int i = 0; i < 4; i++) {
            float s0 = s[i][0] * scale, s1 = s[i][1] * scale;
            float mloc = fmaxf(s0, s1);
#pragma unroll
            for (int off = 8; off > 0; off >>= 1)
                mloc = fmaxf(mloc, __shfl_xor_sync(0xffffffffu, mloc, off));
            float mnew = fmaxf(m_run[i], mloc);
            float corr = expf(m_run[i] - mnew);
            l_run[i] *= corr;
#pragma unroll
            for (int j = 0; j < 4; j++) accO[i][j] *= corr;
            float p0 = expf(s0 - mnew), p1 = expf(s1 - mnew);
            Ps[ty * 4 + i][tx * 2 + 0] = p0;
            Ps[ty * 4 + i][tx * 2 + 1] = p1;
            float lloc = p0 + p1;
#pragma unroll
            for (int off = 8; off > 0; off >>= 1)
                lloc += __shfl_xor_sync(0xffffffffu, lloc, off);
            l_run[i] += lloc;
            m_run[i] = mnew;
        }
        __syncthreads();
        // O += P V : cols tx*4..tx*4+3 via float4 V
#pragma unroll
        for (int kk = 0; kk < 32; kk++) {
            float4 vv = *reinterpret_cast<const float4*>(&Vs[kk][tx * 4]);
#pragma unroll
            for (int i = 0; i < 4; i++) {
                float pv = Ps[ty * 4 + i][kk];
                accO[i][0] += pv * vv.x;
                accO[i][1] += pv * vv.y;
                accO[i][2] += pv * vv.z;
                accO[i][3] += pv * vv.w;
            }
        }
        __syncthreads();
    }

#pragma unroll
    for (int i = 0; i < 4; i++) {
        float inv_l = 1.0f / l_run[i];
        int r = q0 + ty * 4 + i;
        float4 ov = make_float4(accO[i][0] * inv_l, accO[i][1] * inv_l,
                                accO[i][2] * inv_l, accO[i][3] * inv_l);
        *reinterpret_cast<float4*>(&o[(size_t)r * (PH * PDH) + h * PDH + tx * 4]) = ov;
    }
}

// ---------------- fused state-update elementwise ----------------
__global__ void fuse1_kernel(const float* __restrict__ co, const float* __restrict__ velocity,
                             const float* __restrict__ o, const float* __restrict__ mu_cur,
                             const float* __restrict__ hidden_in,
                             float* __restrict__ out_vnext, float* __restrict__ hidmid) {
    size_t i = (size_t)blockIdx.x * blockDim.x + threadIdx.x;
    if (i >= (size_t)PN * PD) return;
    int n = (int)(i / PD), d = (int)(i % PD);
    const float* cor = co + (size_t)n * 3 * PD;
    float alpha = sigmoidf_(cor[d]);
    float beta  = fminf(softplusf_(cor[PD + d]), 2.0f);
    float gate  = sigmoidf_(cor[2 * PD + d]);
    float ov = o[i], mc = mu_cur[i], vel = velocity[i];
    float err = ov - mc;
    float vn = alpha * vel - beta * err;
    vn = fminf(fmaxf(vn, -10.0f), 10.0f);
    out_vnext[i] = vn;
    hidmid[i] = hidden_in[i] + ov + P_DT * gate * vn;
}

// ---------------- router: warp per token ----------------
__global__ void router_kernel(const float* __restrict__ mu_cur, const float* __restrict__ w,
                              const int* __restrict__ token_ids) {
    int tkn = blockIdx.x * 8 + (threadIdx.x >> 5);
    if (tkn >= PN) return;
    int lane = threadIdx.x & 31;
    float lg[PE];
#pragma unroll
    for (int e = 0; e < PE; e++) lg[e] = 0.0f;
    const float* xr = mu_cur + (size_t)tkn * PD;
    for (int d = lane; d < PD; d += 32) {
        float xv = xr[d];
        const float* wr = w + (size_t)d * PE;
#pragma unroll
        for (int e = 0; e < PE; e++) lg[e] += xv * wr[e];
    }
#pragma unroll
    for (int e = 0; e < PE; e++) {
#pragma unroll
        for (int off = 16; off > 0; off >>= 1)
            lg[e] += __shfl_xor_sync(0xffffffffu, lg[e], off);
    }
    if (lane == 0) {
        int b = token_ids[tkn] % PE;
        lg[b] += P_BASE_SCALE;
        int best = 0; float bv = lg[0];
#pragma unroll
        for (int e = 1; e < PE; e++) {
            if (lg[e] > bv) { bv = lg[e]; best = e; }
        }
        int slot = atomicAdd(&g_ecount[best], 1);
        g_elist[best * PN + slot] = tkn;
    }
}

// ---------------- SiLU(G)*U elementwise ----------------
__global__ void midcombine_kernel() {
    size_t i = (size_t)blockIdx.x * blockDim.x + threadIdx.x;
    if (i >= (size_t)PN * PF) return;
    float gv = g_G[i];
    g_mid[i] = (gv / (1.0f + expf(-gv))) * g_U[i];
}

// ---------------- host launch ----------------
static inline void* sym_addr(const void* sym) {
    void* p = nullptr;
    cudaGetSymbolAddress(&p, sym);
    return p;
}

extern "C" void kernel_launch(void* const* d_in, const int* in_sizes, int n_in,
                              void* d_out, int out_size) {
    const float* hidden    = (const float*)d_in[0];
    const int*   positions = (const int*)d_in[1];
    const float* velocity  = (const float*)d_in[2];
    const int*   token_ids = (const int*)d_in[3];
    const float* mu_prev   = (const float*)d_in[4];
    const float* ln1_w     = (const float*)d_in[5];
    const float* ln2_w     = (const float*)d_in[6];
    const float* wq        = (const float*)d_in[7];
    const float* wk        = (const float*)d_in[8];
    const float* wv        = (const float*)d_in[9];
    const float* wo        = (const float*)d_in[10];
    const float* w_mu_q    = (const float*)d_in[11];
    const float* w_mu_k    = (const float*)d_in[12];
    const float* w_mu_v    = (const float*)d_in[13];
    const float* qnorm_w   = (const float*)d_in[14];
    const float* knorm_w   = (const float*)d_in[15];
    const float* dyn_mu    = (const float*)d_in[16];
    const float* dyn_proj  = (const float*)d_in[17];
    const float* ctrl_in_w = (const float*)d_in[18];
    const float* ctrl_in_b = (const float*)d_in[19];
    const float* ctrl_out_w= (const float*)d_in[20];
    const float* ctrl_out_b= (const float*)d_in[21];
    const float* mu_router = (const float*)d_in[22];
    const float* w_gate    = (const float*)d_in[23];
    const float* w_up      = (const float*)d_in[24];
    const float* w_down    = (const float*)d_in[25];

    float* out_hidden = (float*)d_out;
    float* out_vnext  = out_hidden + (size_t)PN * PD;
    float* out_mucur  = out_vnext  + (size_t)PN * PD;

    float* p_hnorm  = (float*)sym_addr(g_hnorm);
    float* p_q      = (float*)sym_addr(g_q);
    float* p_k      = (float*)sym_addr(g_k);
    float* p_v      = (float*)sym_addr(g_v);
    float* p_attno  = (float*)sym_addr(g_attno);
    float* p_o      = (float*)sym_addr(g_o);
    float* p_ctrl   = (float*)sym_addr(g_ctrl);
    float* p_co     = (float*)sym_addr(g_co);
    float* p_hidmid = (float*)sym_addr(g_hidmid);
    float* p_xnorm  = (float*)sym_addr(g_xnorm);
    float* p_G      = (float*)sym_addr(g_G);
    float* p_U      = (float*)sym_addr(g_U);
    float* p_mid    = (float*)sym_addr(g_mid);
    int*   p_elist  = (int*)sym_addr(g_elist);
    int*   p_ecount = (int*)sym_addr(g_ecount);

    zero_counts_kernel<<<1, 32>>>();
    rope_table_kernel<<<(PN * 32 + 255) / 256, 256>>>(positions);
    rmsnorm_kernel<<<PN, 256>>>(hidden, ln1_w, p_hnorm);

    // fused dual-input projections (concat-K): q = h@wq + mu_prev@w_mu_q, etc.
    dim3 gq((PH * PDH + 127) / 128, (PN + 127) / 128);
    tf32_gemm_kernel<<<gq, 256>>>(p_hnorm, wq, mu_prev, w_mu_q, nullptr, nullptr, nullptr, nullptr,
                                  p_q, PN, PH * PDH, 2 * PD, PD, 0);
    dim3 gk((PKV * PDH + 127) / 128, (PN + 127) / 128);
    tf32_gemm_kernel<<<gk, 256>>>(p_hnorm, wk, mu_prev, w_mu_k, nullptr, nullptr, nullptr, nullptr,
                                  p_k, PN, PKV * PDH, 2 * PD, PD, 0);
    tf32_gemm_kernel<<<gk, 256>>>(p_hnorm, wv, mu_prev, w_mu_v, nullptr, nullptr, nullptr, nullptr,
                                  p_v, PN, PKV * PDH, 2 * PD, PD, 0);

    qknorm_rope_kernel<<<(PN * PH + 7) / 8, 256>>>(p_q, qnorm_w, PH, PN * PH);
    qknorm_rope_kernel<<<(PN * PKV + 7) / 8, 256>>>(p_k, knorm_w, PKV, PN * PKV);

    attn_kernel<<<dim3(PN / 64, PH), 256>>>(p_q, p_k, p_v, p_attno);

    // o = attno @ wo
    dim3 go((PD + 127) / 128, (PN + 127) / 128);
    tf32_gemm_kernel<<<go, 256>>>(p_attno, wo, nullptr, nullptr, nullptr, nullptr, nullptr, nullptr,
                                  p_o, PN, PD, PD, PD, 0);

    // ctrl = silu([o, velocity] @ ctrl_in_w + b)  (concat-K, fused)
    dim3 gc(1, (PN + 127) / 128);
    tf32_gemm_kernel<<<gc, 256>>>(p_o, ctrl_in_w, velocity, ctrl_in_w + PD * PCH, ctrl_in_b,
                                  nullptr, nullptr, nullptr, p_ctrl, PN, PCH, 2 * PD, PD, 2);

    // co = ctrl @ ctrl_out_w + ctrl_out_b
    dim3 gco((3 * PD + 127) / 128, (PN + 127) / 128);
    tf32_gemm_kernel<<<gco, 256>>>(p_ctrl, ctrl_out_w, nullptr, nullptr, ctrl_out_b,
                                   nullptr, nullptr, nullptr, p_co, PN, 3 * PD, PCH, PCH, 0);

    // mu_cur = dyn_mu + o @ dyn_mu_proj_w
    tf32_gemm_kernel<<<go, 256>>>(p_o, dyn_proj, nullptr, nullptr, dyn_mu,
                                  nullptr, nullptr, nullptr, out_mucur, PN, PD, PD, PD, 0);

    fuse1_kernel<<<(PN * PD + 255) / 256, 256>>>(p_co, velocity, p_o, out_mucur, hidden,
                                                 out_vnext, p_hidmid);

    rmsnorm_kernel<<<PN, 256>>>(p_hidmid, ln2_w, p_xnorm);
    router_kernel<<<(PN + 7) / 8, 256>>>(out_mucur, mu_router, token_ids);

    // MoE stage 1: G = x@w_gate[e], U = x@w_up[e]
    dim3 gm1((PF + 127) / 128, (PN + 127) / 128);
    for (int e = 0; e < PE; e++) {
        tf32_gemm_kernel<<<gm1, 256>>>(p_xnorm, w_gate + (size_t)e * PD * PF, nullptr, nullptr,
                                       nullptr, p_elist + e * PN, p_ecount + e, nullptr,
                                       p_G, PN, PF, PD, PD, 0);
        tf32_gemm_kernel<<<gm1, 256>>>(p_xnorm, w_up + (size_t)e * PD * PF, nullptr, nullptr,
                                       nullptr, p_elist + e * PN, p_ecount + e, nullptr,
                                       p_U, PN, PF, PD, PD, 0);
    }
    midcombine_kernel<<<(PN * PF + 255) / 256, 256>>>();

    // MoE stage 2: hidden_out = hidmid + mid@w_down[e]
    dim3 gm2((PD + 127) / 128, (PN + 127) / 128);
    for (int e = 0; e < PE; e++) {
        tf32_gemm_kernel<<<gm2, 256>>>(p_mid, w_down + (size_t)e * PF * PD, nullptr, nullptr,
                                       nullptr, p_elist + e * PN, p_ecount + e, p_hidmid,
                                       out_hidden, PN, PD, PF, PF, 0);
    }
}

// round 4
// speedup vs baseline: 4.5052x; 1.4761x over previous
#include <cuda_runtime.h>
#include <math.h>
#include <stdint.h>

// ---------------- problem constants ----------------
#define PN   2048
#define PD   1024
#define PH   16
#define PKV  4
#define PDH  64
#define PE   8
#define PF   2048
#define PCH  64
#define P_EPS 1e-6f
#define P_DT  0.1f
#define P_BASE_SCALE 10.0f

// ---------------- scratch ----------------
__device__ float g_hnorm[PN * PD];
__device__ float g_q[PN * PH * PDH];
__device__ float g_k[PN * PKV * PDH];
__device__ float g_v[PN * PKV * PDH];
__device__ float g_attno[PN * PD];
__device__ float g_o[PN * PD];
__device__ float g_ctrl[PN * PCH];
__device__ float g_co[PN * 3 * PD];
__device__ float g_hidmid[PN * PD];
__device__ float g_xnorm[PN * PD];
__device__ float g_G[PN * PF];
__device__ float g_U[PN * PF];
__device__ float g_mid[PN * PF];
__device__ float g_cosT[PN * 32];
__device__ float g_sinT[PN * 32];
__device__ int   g_elist[PE * PN];
__device__ int   g_ecount[PE];

// ---------------- helpers ----------------
__device__ __forceinline__ float sigmoidf_(float x) { return 1.0f / (1.0f + expf(-x)); }
__device__ __forceinline__ float softplusf_(float x) {
    return fmaxf(x, 0.0f) + log1pf(expf(-fabsf(x)));
}
__device__ __forceinline__ uint32_t f2tf32(float f) {
    uint32_t r; asm("cvt.rna.tf32.f32 %0, %1;" : "=r"(r) : "f"(f)); return r;
}
__device__ __forceinline__ void mma_tf32(float* d, const uint32_t* a, const uint32_t* b) {
    asm volatile(
        "mma.sync.aligned.m16n8k8.row.col.f32.tf32.tf32.f32 "
        "{%0,%1,%2,%3}, {%4,%5,%6,%7}, {%8,%9}, {%0,%1,%2,%3};"
        : "+f"(d[0]), "+f"(d[1]), "+f"(d[2]), "+f"(d[3])
        : "r"(a[0]), "r"(a[1]), "r"(a[2]), "r"(a[3]), "r"(b[0]), "r"(b[1]));
}

__global__ void zero_counts_kernel() {
    int t = threadIdx.x;
    if (t < PE) g_ecount[t] = 0;
}

__global__ void rope_table_kernel(const int* __restrict__ positions) {
    __shared__ float sm_inv[32];
    if (threadIdx.x < 32) {
        double inv = pow(10000.0, -((double)(2 * threadIdx.x)) / 64.0);
        sm_inv[threadIdx.x] = (float)inv;
    }
    __syncthreads();
    int i = blockIdx.x * 256 + threadIdx.x;
    if (i >= PN * 32) return;
    int n = i >> 5, f = i & 31;
    float ang = (float)positions[n] * sm_inv[f];
    float s, c;
    sincosf(ang, &s, &c);
    g_cosT[i] = c;
    g_sinT[i] = s;
}

__global__ void rmsnorm_kernel(const float* __restrict__ x, const float* __restrict__ w,
                               float* __restrict__ out) {
    int row = blockIdx.x;
    int tid = threadIdx.x;
    __shared__ float red[256];
    const float* xr = x + (size_t)row * PD;
    float s = 0.0f;
    for (int d = tid; d < PD; d += 256) { float v = xr[d]; s += v * v; }
    red[tid] = s; __syncthreads();
    for (int off = 128; off > 0; off >>= 1) {
        if (tid < off) red[tid] += red[tid + off];
        __syncthreads();
    }
    float scale = rsqrtf(red[0] / (float)PD + P_EPS);
    float* orow = out + (size_t)row * PD;
    for (int d = tid; d < PD; d += 256) orow[d] = xr[d] * scale * w[d];
}

// ---------------- multi-descriptor TF32 GEMM (M = PN fixed, no gather) ----------------
struct GDesc {
    const float* A; const float* A2;     // concat-K inputs (A2 may be null)
    const float* B; const float* B2;
    const float* bias;
    float* C;
    int Nc; int K; int K1; int flags;    // flags bit1: SiLU
};

__global__ __launch_bounds__(256, 2)
void tf32_gemm_multi(GDesc d0, GDesc d1, GDesc d2) {
    __shared__ uint32_t As[2][128][20];
    __shared__ uint32_t Bs[2][16][136];

    GDesc d = (blockIdx.z == 0) ? d0 : ((blockIdx.z == 1) ? d1 : d2);
    int m0 = blockIdx.y * 128;
    int n0 = blockIdx.x * 128;
    if (n0 >= d.Nc) return;

    int tid  = threadIdx.x;
    int lane = tid & 31;
    int w    = tid >> 5;
    int wm   = w >> 1;
    int wn   = w & 1;

    int a_r  = tid >> 2;
    int a_kq = (tid & 3) * 4;
    int b_k  = tid >> 5;
    int b_nq = (tid & 31) * 4;

    float4 aV[2], bV[2];
    float acc[2][8][4];
#pragma unroll
    for (int mf = 0; mf < 2; mf++)
#pragma unroll
        for (int nf = 0; nf < 8; nf++)
#pragma unroll
            for (int c = 0; c < 4; c++) acc[mf][nf][c] = 0.0f;

    auto loadA = [&](int k0) {
        const float* Ap = d.A; int lda = d.K1; int kk = k0;
        if (k0 >= d.K1) { Ap = d.A2; lda = d.K - d.K1; kk = k0 - d.K1; }
#pragma unroll
        for (int i = 0; i < 2; i++) {
            int pos = m0 + a_r + i * 64;
            aV[i] = *reinterpret_cast<const float4*>(&Ap[(size_t)pos * lda + kk + a_kq]);
        }
    };
    auto loadB = [&](int k0) {
        const float* Bp = d.B; int kk = k0;
        if (k0 >= d.K1) { Bp = d.B2; kk = k0 - d.K1; }
        int col = n0 + b_nq;
#pragma unroll
        for (int i = 0; i < 2; i++) {
            if (col < d.Nc) {
                bV[i] = *reinterpret_cast<const float4*>(&Bp[(size_t)(kk + b_k + i * 8) * d.Nc + col]);
            } else {
                bV[i] = make_float4(0.f, 0.f, 0.f, 0.f);
            }
        }
    };
    auto stsTile = [&](int buf) {
#pragma unroll
        for (int i = 0; i < 2; i++) {
            int r = a_r + i * 64;
            As[buf][r][a_kq + 0] = f2tf32(aV[i].x);
            As[buf][r][a_kq + 1] = f2tf32(aV[i].y);
            As[buf][r][a_kq + 2] = f2tf32(aV[i].z);
            As[buf][r][a_kq + 3] = f2tf32(aV[i].w);
        }
#pragma unroll
        for (int i = 0; i < 2; i++) {
            int kr = b_k + i * 8;
            Bs[buf][kr][b_nq + 0] = f2tf32(bV[i].x);
            Bs[buf][kr][b_nq + 1] = f2tf32(bV[i].y);
            Bs[buf][kr][b_nq + 2] = f2tf32(bV[i].z);
            Bs[buf][kr][b_nq + 3] = f2tf32(bV[i].w);
        }
    };

    loadA(0); loadB(0);
    stsTile(0);
    __syncthreads();

    int buf = 0;
    for (int k0 = 16; k0 <= d.K; k0 += 16) {
        bool nxt = (k0 < d.K);
        if (nxt) { loadA(k0); loadB(k0); }
#pragma unroll
        for (int s = 0; s < 2; s++) {
            uint32_t afr[2][4], bfr[8][2];
            int kk = s * 8 + (lane & 3);
#pragma unroll
            for (int mf = 0; mf < 2; mf++) {
                int rb = wm * 32 + mf * 16 + (lane >> 2);
                afr[mf][0] = As[buf][rb][kk];
                afr[mf][1] = As[buf][rb + 8][kk];
                afr[mf][2] = As[buf][rb][kk + 4];
                afr[mf][3] = As[buf][rb + 8][kk + 4];
            }
#pragma unroll
            for (int nf = 0; nf < 8; nf++) {
                int cb = wn * 64 + nf * 8 + (lane >> 2);
                bfr[nf][0] = Bs[buf][kk][cb];
                bfr[nf][1] = Bs[buf][kk + 4][cb];
            }
#pragma unroll
            for (int mf = 0; mf < 2; mf++)
#pragma unroll
                for (int nf = 0; nf < 8; nf++)
                    mma_tf32(acc[mf][nf], afr[mf], bfr[nf]);
        }
        if (nxt) stsTile(buf ^ 1);
        __syncthreads();
        buf ^= 1;
    }

#pragma unroll
    for (int mf = 0; mf < 2; mf++) {
#pragma unroll
        for (int r2 = 0; r2 < 2; r2++) {
            int crow = m0 + wm * 32 + mf * 16 + (lane >> 2) + r2 * 8;
#pragma unroll
            for (int nf = 0; nf < 8; nf++) {
#pragma unroll
                for (int c2 = 0; c2 < 2; c2++) {
                    int col = n0 + wn * 64 + nf * 8 + (lane & 3) * 2 + c2;
                    if (col >= d.Nc) continue;
                    size_t ci = (size_t)crow * d.Nc + col;
                    float val = acc[mf][nf][r2 * 2 + c2];
                    if (d.bias) val += d.bias[col];
                    if (d.flags & 2) val = val / (1.0f + expf(-val));
                    d.C[ci] = val;
                }
            }
        }
    }
}

// ---------------- MoE GEMM: grid.z = expert, gate/up split along x ----------------
// part 0 (x < xPart): B = Bg + e*bStride, C = Cg ; part 1: Bu, Cu.
__global__ __launch_bounds__(256, 2)
void moe_gemm_kernel(const float* __restrict__ A,
                     const float* __restrict__ Bg, const float* __restrict__ Bu,
                     size_t bStride, float* __restrict__ Cg, float* __restrict__ Cu,
                     const float* __restrict__ residual,
                     int Nc, int K, int xPart) {
    __shared__ uint32_t As[2][128][20];
    __shared__ uint32_t Bs[2][16][136];

    int e = blockIdx.z;
    int cnt = g_ecount[e];
    int m0 = blockIdx.y * 128;
    if (m0 >= cnt) return;
    int part = blockIdx.x / xPart;
    int n0 = (blockIdx.x % xPart) * 128;
    const float* B = (part ? Bu : Bg) + (size_t)e * bStride;
    float* C = part ? Cu : Cg;
    const int* gather = g_elist + e * PN;

    int tid  = threadIdx.x;
    int lane = tid & 31;
    int w    = tid >> 5;
    int wm   = w >> 1;
    int wn   = w & 1;

    int a_r  = tid >> 2;
    int a_kq = (tid & 3) * 4;
    int b_k  = tid >> 5;
    int b_nq = (tid & 31) * 4;

    float4 aV[2], bV[2];
    float acc[2][8][4];
#pragma unroll
    for (int mf = 0; mf < 2; mf++)
#pragma unroll
        for (int nf = 0; nf < 8; nf++)
#pragma unroll
            for (int c = 0; c < 4; c++) acc[mf][nf][c] = 0.0f;

    auto loadA = [&](int k0) {
#pragma unroll
        for (int i = 0; i < 2; i++) {
            int pos = m0 + a_r + i * 64;
            if (pos < cnt) {
                int ar = gather[pos];
                aV[i] = *reinterpret_cast<const float4*>(&A[(size_t)ar * K + k0 + a_kq]);
            } else {
                aV[i] = make_float4(0.f, 0.f, 0.f, 0.f);
            }
        }
    };
    auto loadB = [&](int k0) {
        int col = n0 + b_nq;
#pragma unroll
        for (int i = 0; i < 2; i++)
            bV[i] = *reinterpret_cast<const float4*>(&B[(size_t)(k0 + b_k + i * 8) * Nc + col]);
    };
    auto stsTile = [&](int buf) {
#pragma unroll
        for (int i = 0; i < 2; i++) {
            int r = a_r + i * 64;
            As[buf][r][a_kq + 0] = f2tf32(aV[i].x);
            As[buf][r][a_kq + 1] = f2tf32(aV[i].y);
            As[buf][r][a_kq + 2] = f2tf32(aV[i].z);
            As[buf][r][a_kq + 3] = f2tf32(aV[i].w);
        }
#pragma unroll
        for (int i = 0; i < 2; i++) {
            int kr = b_k + i * 8;
            Bs[buf][kr][b_nq + 0] = f2tf32(bV[i].x);
            Bs[buf][kr][b_nq + 1] = f2tf32(bV[i].y);
            Bs[buf][kr][b_nq + 2] = f2tf32(bV[i].z);
            Bs[buf][kr][b_nq + 3] = f2tf32(bV[i].w);
        }
    };

    loadA(0); loadB(0);
    stsTile(0);
    __syncthreads();

    int buf = 0;
    for (int k0 = 16; k0 <= K; k0 += 16) {
        bool nxt = (k0 < K);
        if (nxt) { loadA(k0); loadB(k0); }
#pragma unroll
        for (int s = 0; s < 2; s++) {
            uint32_t afr[2][4], bfr[8][2];
            int kk = s * 8 + (lane & 3);
#pragma unroll
            for (int mf = 0; mf < 2; mf++) {
                int rb = wm * 32 + mf * 16 + (lane >> 2);
                afr[mf][0] = As[buf][rb][kk];
                afr[mf][1] = As[buf][rb + 8][kk];
                afr[mf][2] = As[buf][rb][kk + 4];
                afr[mf][3] = As[buf][rb + 8][kk + 4];
            }
#pragma unroll
            for (int nf = 0; nf < 8; nf++) {
                int cb = wn * 64 + nf * 8 + (lane >> 2);
                bfr[nf][0] = Bs[buf][kk][cb];
                bfr[nf][1] = Bs[buf][kk + 4][cb];
            }
#pragma unroll
            for (int mf = 0; mf < 2; mf++)
#pragma unroll
                for (int nf = 0; nf < 8; nf++)
                    mma_tf32(acc[mf][nf], afr[mf], bfr[nf]);
        }
        if (nxt) stsTile(buf ^ 1);
        __syncthreads();
        buf ^= 1;
    }

#pragma unroll
    for (int mf = 0; mf < 2; mf++) {
#pragma unroll
        for (int r2 = 0; r2 < 2; r2++) {
            int pos = m0 + wm * 32 + mf * 16 + (lane >> 2) + r2 * 8;
            if (pos >= cnt) continue;
            int crow = gather[pos];
#pragma unroll
            for (int nf = 0; nf < 8; nf++) {
#pragma unroll
                for (int c2 = 0; c2 < 2; c2++) {
                    int col = n0 + wn * 64 + nf * 8 + (lane & 3) * 2 + c2;
                    size_t ci = (size_t)crow * Nc + col;
                    float val = acc[mf][nf][r2 * 2 + c2];
                    if (residual) val += residual[ci];
                    C[ci] = val;
                }
            }
        }
    }
}

// ---------------- per-head RMSNorm + RoPE ----------------
__global__ void qknorm_rope_kernel(float* __restrict__ x, const float* __restrict__ w,
                                   int heads, int nrows) {
    int row = blockIdx.x * 8 + (threadIdx.x >> 5);
    if (row >= nrows) return;
    int lane = threadIdx.x & 31;
    int n = row / heads;
    float* base = x + (size_t)row * PDH;
    float x1 = base[lane];
    float x2 = base[lane + 32];
    float s = x1 * x1 + x2 * x2;
#pragma unroll
    for (int off = 16; off > 0; off >>= 1) s += __shfl_xor_sync(0xffffffffu, s, off);
    float scale = rsqrtf(s / (float)PDH + P_EPS);
    x1 *= scale * w[lane];
    x2 *= scale * w[lane + 32];
    float c  = g_cosT[n * 32 + lane];
    float sn = g_sinT[n * 32 + lane];
    base[lane]      = x1 * c - x2 * sn;
    base[lane + 32] = x2 * c + x1 * sn;
}

// ---------------- flash attention: 64-query blocks, 32-key tiles, vectorized ----------------
__global__ __launch_bounds__(256, 2)
void attn_kernel(const float* __restrict__ q, const float* __restrict__ k,
                 const float* __restrict__ v, float* __restrict__ o) {
    __shared__ float Qs[64][64];
    __shared__ float Ks[32][65];
    __shared__ float Vs[32][64];
    __shared__ float Ps[64][33];

    int qb = blockIdx.x, h = blockIdx.y;
    int kvh = h / (PH / PKV);
    int q0 = qb * 64;
    int tid = threadIdx.x;
    int tx = tid % 16, ty = tid / 16;

    for (int i = tid; i < 64 * 16; i += 256) {
        int r = i >> 4, d4 = (i & 15) * 4;
        *reinterpret_cast<float4*>(&Qs[r][d4]) =
            *reinterpret_cast<const float4*>(&q[(size_t)(q0 + r) * (PH * PDH) + h * PDH + d4]);
    }

    float accO[4][4];
    float m_run[4], l_run[4];
#pragma unroll
    for (int i = 0; i < 4; i++) {
        m_run[i] = -INFINITY; l_run[i] = 0.0f;
#pragma unroll
        for (int j = 0; j < 4; j++) accO[i][j] = 0.0f;
    }
    __syncthreads();

    const float scale = 0.125f;
    for (int t = 0; t < PN / 32; t++) {
        for (int i = tid; i < 32 * 16; i += 256) {
            int r = i >> 4, d4 = (i & 15) * 4;
            size_t gi = (size_t)(t * 32 + r) * (PKV * PDH) + kvh * PDH + d4;
            float4 kv = *reinterpret_cast<const float4*>(&k[gi]);
            Ks[r][d4 + 0] = kv.x; Ks[r][d4 + 1] = kv.y;
            Ks[r][d4 + 2] = kv.z; Ks[r][d4 + 3] = kv.w;
            *reinterpret_cast<float4*>(&Vs[r][d4]) = *reinterpret_cast<const float4*>(&v[gi]);
        }
        __syncthreads();

        float s[4][2];
#pragma unroll
        for (int i = 0; i < 4; i++) { s[i][0] = 0.0f; s[i][1] = 0.0f; }
#pragma unroll
        for (int d4 = 0; d4 < 16; d4++) {
            float4 aq[4];
#pragma unroll
            for (int i = 0; i < 4; i++)
                aq[i] = *reinterpret_cast<const float4*>(&Qs[ty * 4 + i][d4 * 4]);
#pragma unroll
            for (int j = 0; j < 2; j++) {
                int kr = tx * 2 + j;
                float b0 = Ks[kr][d4 * 4 + 0], b1 = Ks[kr][d4 * 4 + 1];
                float b2 = Ks[kr][d4 * 4 + 2], b3 = Ks[kr][d4 * 4 + 3];
#pragma unroll
                for (int i = 0; i < 4; i++) {
                    s[i][j] += aq[i].x * b0 + aq[i].y * b1 + aq[i].z * b2 + aq[i].w * b3;
                }
            }
        }
#pragma unroll
        for (int i = 0; i < 4; i++) {
            float s0 = s[i][0] * scale, s1 = s[i][1] * scale;
            float mloc = fmaxf(s0, s1);
#pragma unroll
            for (int off = 8; off > 0; off >>= 1)
                mloc = fmaxf(mloc, __shfl_xor_sync(0xffffffffu, mloc, off));
            float mnew = fmaxf(m_run[i], mloc);
            float corr = expf(m_run[i] - mnew);
            l_run[i] *= corr;
#pragma unroll
            for (int j = 0; j < 4; j++) accO[i][j] *= corr;
            float p0 = expf(s0 - mnew), p1 = expf(s1 - mnew);
            Ps[ty * 4 + i][tx * 2 + 0] = p0;
            Ps[ty * 4 + i][tx * 2 + 1] = p1;
            float lloc = p0 + p1;
#pragma unroll
            for (int off = 8; off > 0; off >>= 1)
                lloc += __shfl_xor_sync(0xffffffffu, lloc, off);
            l_run[i] += lloc;
            m_run[i] = mnew;
        }
        __syncthreads();
#pragma unroll
        for (int kk = 0; kk < 32; kk++) {
            float4 vv = *reinterpret_cast<const float4*>(&Vs[kk][tx * 4]);
#pragma unroll
            for (int i = 0; i < 4; i++) {
                float pv = Ps[ty * 4 + i][kk];
                accO[i][0] += pv * vv.x;
                accO[i][1] += pv * vv.y;
                accO[i][2] += pv * vv.z;
                accO[i][3] += pv * vv.w;
            }
        }
        __syncthreads();
    }

#pragma unroll
    for (int i = 0; i < 4; i++) {
        float inv_l = 1.0f / l_run[i];
        int r = q0 + ty * 4 + i;
        float4 ov = make_float4(accO[i][0] * inv_l, accO[i][1] * inv_l,
                                accO[i][2] * inv_l, accO[i][3] * inv_l);
        *reinterpret_cast<float4*>(&o[(size_t)r * (PH * PDH) + h * PDH + tx * 4]) = ov;
    }
}

// ---------------- fused state-update ----------------
__global__ void fuse1_kernel(const float* __restrict__ co, const float* __restrict__ velocity,
                             const float* __restrict__ o, const float* __restrict__ mu_cur,
                             const float* __restrict__ hidden_in,
                             float* __restrict__ out_vnext, float* __restrict__ hidmid) {
    size_t i = (size_t)blockIdx.x * blockDim.x + threadIdx.x;
    if (i >= (size_t)PN * PD) return;
    int n = (int)(i / PD), d = (int)(i % PD);
    const float* cor = co + (size_t)n * 3 * PD;
    float alpha = sigmoidf_(cor[d]);
    float beta  = fminf(softplusf_(cor[PD + d]), 2.0f);
    float gate  = sigmoidf_(cor[2 * PD + d]);
    float ov = o[i], mc = mu_cur[i], vel = velocity[i];
    float err = ov - mc;
    float vn = alpha * vel - beta * err;
    vn = fminf(fmaxf(vn, -10.0f), 10.0f);
    out_vnext[i] = vn;
    hidmid[i] = hidden_in[i] + ov + P_DT * gate * vn;
}

// ---------------- router ----------------
__global__ void router_kernel(const float* __restrict__ mu_cur, const float* __restrict__ w,
                              const int* __restrict__ token_ids) {
    int tkn = blockIdx.x * 8 + (threadIdx.x >> 5);
    if (tkn >= PN) return;
    int lane = threadIdx.x & 31;
    float lg[PE];
#pragma unroll
    for (int e = 0; e < PE; e++) lg[e] = 0.0f;
    const float* xr = mu_cur + (size_t)tkn * PD;
    for (int d = lane; d < PD; d += 32) {
        float xv = xr[d];
        const float* wr = w + (size_t)d * PE;
#pragma unroll
        for (int e = 0; e < PE; e++) lg[e] += xv * wr[e];
    }
#pragma unroll
    for (int e = 0; e < PE; e++) {
#pragma unroll
        for (int off = 16; off > 0; off >>= 1)
            lg[e] += __shfl_xor_sync(0xffffffffu, lg[e], off);
    }
    if (lane == 0) {
        int b = token_ids[tkn] % PE;
        lg[b] += P_BASE_SCALE;
        int best = 0; float bv = lg[0];
#pragma unroll
        for (int e = 1; e < PE; e++) {
            if (lg[e] > bv) { bv = lg[e]; best = e; }
        }
        int slot = atomicAdd(&g_ecount[best], 1);
        g_elist[best * PN + slot] = tkn;
    }
}

__global__ void midcombine_kernel() {
    size_t i = (size_t)blockIdx.x * blockDim.x + threadIdx.x;
    if (i >= (size_t)PN * PF) return;
    float gv = g_G[i];
    g_mid[i] = (gv / (1.0f + expf(-gv))) * g_U[i];
}

// ---------------- host launch ----------------
static inline void* sym_addr(const void* sym) {
    void* p = nullptr;
    cudaGetSymbolAddress(&p, sym);
    return p;
}

extern "C" void kernel_launch(void* const* d_in, const int* in_sizes, int n_in,
                              void* d_out, int out_size) {
    const float* hidden    = (const float*)d_in[0];
    const int*   positions = (const int*)d_in[1];
    const float* velocity  = (const float*)d_in[2];
    const int*   token_ids = (const int*)d_in[3];
    const float* mu_prev   = (const float*)d_in[4];
    const float* ln1_w     = (const float*)d_in[5];
    const float* ln2_w     = (const float*)d_in[6];
    const float* wq        = (const float*)d_in[7];
    const float* wk        = (const float*)d_in[8];
    const float* wv        = (const float*)d_in[9];
    const float* wo        = (const float*)d_in[10];
    const float* w_mu_q    = (const float*)d_in[11];
    const float* w_mu_k    = (const float*)d_in[12];
    const float* w_mu_v    = (const float*)d_in[13];
    const float* qnorm_w   = (const float*)d_in[14];
    const float* knorm_w   = (const float*)d_in[15];
    const float* dyn_mu    = (const float*)d_in[16];
    const float* dyn_proj  = (const float*)d_in[17];
    const float* ctrl_in_w = (const float*)d_in[18];
    const float* ctrl_in_b = (const float*)d_in[19];
    const float* ctrl_out_w= (const float*)d_in[20];
    const float* ctrl_out_b= (const float*)d_in[21];
    const float* mu_router = (const float*)d_in[22];
    const float* w_gate    = (const float*)d_in[23];
    const float* w_up      = (const float*)d_in[24];
    const float* w_down    = (const float*)d_in[25];

    float* out_hidden = (float*)d_out;
    float* out_vnext  = out_hidden + (size_t)PN * PD;
    float* out_mucur  = out_vnext  + (size_t)PN * PD;

    float* p_hnorm  = (float*)sym_addr(g_hnorm);
    float* p_q      = (float*)sym_addr(g_q);
    float* p_k      = (float*)sym_addr(g_k);
    float* p_v      = (float*)sym_addr(g_v);
    float* p_attno  = (float*)sym_addr(g_attno);
    float* p_o      = (float*)sym_addr(g_o);
    float* p_ctrl   = (float*)sym_addr(g_ctrl);
    float* p_co     = (float*)sym_addr(g_co);
    float* p_hidmid = (float*)sym_addr(g_hidmid);
    float* p_xnorm  = (float*)sym_addr(g_xnorm);
    float* p_G      = (float*)sym_addr(g_G);
    float* p_U      = (float*)sym_addr(g_U);
    float* p_mid    = (float*)sym_addr(g_mid);

    zero_counts_kernel<<<1, 32>>>();
    rope_table_kernel<<<(PN * 32 + 255) / 256, 256>>>(positions);
    rmsnorm_kernel<<<PN, 256>>>(hidden, ln1_w, p_hnorm);

    // QKV in ONE launch: z=0 q, z=1 k, z=2 v (k/v blocks with n0>=256 early-exit)
    {
        GDesc dq { p_hnorm, mu_prev, wq, w_mu_q, nullptr, p_q, PH * PDH, 2 * PD, PD, 0 };
        GDesc dk { p_hnorm, mu_prev, wk, w_mu_k, nullptr, p_k, PKV * PDH, 2 * PD, PD, 0 };
        GDesc dv { p_hnorm, mu_prev, wv, w_mu_v, nullptr, p_v, PKV * PDH, 2 * PD, PD, 0 };
        tf32_gemm_multi<<<dim3(8, 16, 3), 256>>>(dq, dk, dv);
    }

    qknorm_rope_kernel<<<(PN * PH + 7) / 8, 256>>>(p_q, qnorm_w, PH, PN * PH);
    qknorm_rope_kernel<<<(PN * PKV + 7) / 8, 256>>>(p_k, knorm_w, PKV, PN * PKV);

    attn_kernel<<<dim3(PN / 64, PH), 256>>>(p_q, p_k, p_v, p_attno);

    // o = attno @ wo
    {
        GDesc d { p_attno, nullptr, wo, nullptr, nullptr, p_o, PD, PD, PD, 0 };
        tf32_gemm_multi<<<dim3(8, 16, 1), 256>>>(d, d, d);
    }

    // dyn-proj and ctrl concurrently (both depend only on o)
    {
        GDesc dd { p_o, nullptr, dyn_proj, nullptr, dyn_mu, out_mucur, PD, PD, PD, 0 };
        GDesc dc { p_o, velocity, ctrl_in_w, ctrl_in_w + PD * PCH, ctrl_in_b, p_ctrl,
                   PCH, 2 * PD, PD, 2 };
        tf32_gemm_multi<<<dim3(8, 16, 2), 256>>>(dd, dc, dc);
    }

    // co = ctrl @ ctrl_out_w + ctrl_out_b
    {
        GDesc d { p_ctrl, nullptr, ctrl_out_w, nullptr, ctrl_out_b, p_co, 3 * PD, PCH, PCH, 0 };
        tf32_gemm_multi<<<dim3(24, 16, 1), 256>>>(d, d, d);
    }

    fuse1_kernel<<<(PN * PD + 255) / 256, 256>>>(p_co, velocity, p_o, out_mucur, hidden,
                                                 out_vnext, p_hidmid);

    rmsnorm_kernel<<<PN, 256>>>(p_hidmid, ln2_w, p_xnorm);
    router_kernel<<<(PN + 7) / 8, 256>>>(out_mucur, mu_router, token_ids);

    // MoE stage 1 — single launch over all experts, gate+up fused
    moe_gemm_kernel<<<dim3(32, 16, PE), 256>>>(p_xnorm, w_gate, w_up,
                                               (size_t)PD * PF, p_G, p_U,
                                               nullptr, PF, PD, 16);
    midcombine_kernel<<<(PN * PF + 255) / 256, 256>>>();

    // MoE stage 2 — single launch over all experts
    moe_gemm_kernel<<<dim3(8, 16, PE), 256>>>(p_mid, w_down, nullptr,
                                              (size_t)PF * PD, out_hidden, nullptr,
                                              p_hidmid, PD, PF, 8);
}

// round 5
// speedup vs baseline: 9.8136x; 2.1783x over previous
#include <cuda_runtime.h>
#include <math.h>
#include <stdint.h>

// ---------------- problem constants ----------------
#define PN   2048
#define PD   1024
#define PH   16
#define PKV  4
#define PDH  64
#define PE   8
#define PF   2048
#define PCH  64
#define P_EPS 1e-6f
#define P_DT  0.1f
#define P_BASE_SCALE 10.0f

// ---------------- scratch ----------------
__device__ float g_hnorm[PN * PD];
__device__ float g_q[PN * PH * PDH];
__device__ float g_k[PN * PKV * PDH];
__device__ float g_v[PN * PKV * PDH];
__device__ float g_attno[PN * PD];
__device__ float g_o[PN * PD];
__device__ float g_ctrl[PN * PCH];
__device__ float g_co[PN * 3 * PD];
__device__ float g_hidmid[PN * PD];
__device__ float g_xnorm[PN * PD];
__device__ float g_G[PN * PF];
__device__ float g_U[PN * PF];
__device__ float g_mid[PN * PF];
__device__ float g_cosT[PN * 32];
__device__ float g_sinT[PN * 32];
__device__ int   g_elist[PE * PN];
__device__ int   g_ecount[PE];

// ---------------- helpers ----------------
__device__ __forceinline__ float sigmoidf_(float x) { return 1.0f / (1.0f + expf(-x)); }
__device__ __forceinline__ float softplusf_(float x) {
    return fmaxf(x, 0.0f) + log1pf(expf(-fabsf(x)));
}
__device__ __forceinline__ uint32_t f2tf32(float f) {
    uint32_t r; asm("cvt.rna.tf32.f32 %0, %1;" : "=r"(r) : "f"(f)); return r;
}
__device__ __forceinline__ void mma_tf32(float* d, const uint32_t* a, const uint32_t* b) {
    asm volatile(
        "mma.sync.aligned.m16n8k8.row.col.f32.tf32.tf32.f32 "
        "{%0,%1,%2,%3}, {%4,%5,%6,%7}, {%8,%9}, {%0,%1,%2,%3};"
        : "+f"(d[0]), "+f"(d[1]), "+f"(d[2]), "+f"(d[3])
        : "r"(a[0]), "r"(a[1]), "r"(a[2]), "r"(a[3]), "r"(b[0]), "r"(b[1]));
}

__global__ void zero_counts_kernel() {
    int t = threadIdx.x;
    if (t < PE) g_ecount[t] = 0;
}

__global__ void rope_table_kernel(const int* __restrict__ positions) {
    __shared__ float sm_inv[32];
    if (threadIdx.x < 32) {
        double inv = pow(10000.0, -((double)(2 * threadIdx.x)) / 64.0);
        sm_inv[threadIdx.x] = (float)inv;
    }
    __syncthreads();
    int i = blockIdx.x * 256 + threadIdx.x;
    if (i >= PN * 32) return;
    int n = i >> 5, f = i & 31;
    float ang = (float)positions[n] * sm_inv[f];
    float s, c;
    sincosf(ang, &s, &c);
    g_cosT[i] = c;
    g_sinT[i] = s;
}

__global__ void rmsnorm_kernel(const float* __restrict__ x, const float* __restrict__ w,
                               float* __restrict__ out) {
    int row = blockIdx.x;
    int tid = threadIdx.x;
    __shared__ float red[256];
    const float* xr = x + (size_t)row * PD;
    float s = 0.0f;
    for (int d = tid; d < PD; d += 256) { float v = xr[d]; s += v * v; }
    red[tid] = s; __syncthreads();
    for (int off = 128; off > 0; off >>= 1) {
        if (tid < off) red[tid] += red[tid + off];
        __syncthreads();
    }
    float scale = rsqrtf(red[0] / (float)PD + P_EPS);
    float* orow = out + (size_t)row * PD;
    for (int d = tid; d < PD; d += 256) orow[d] = xr[d] * scale * w[d];
}

// ---------------- multi-descriptor TF32 GEMM ----------------
struct GDesc {
    const float* A; const float* A2;
    const float* B; const float* B2;
    const float* bias;
    float* C;
    int Nc; int K; int K1; int flags;    // flags bit1: SiLU
};

__global__ __launch_bounds__(256, 2)
void tf32_gemm_multi(GDesc d0, GDesc d1, GDesc d2) {
    __shared__ uint32_t As[2][128][20];
    __shared__ uint32_t Bs[2][16][136];

    GDesc d = (blockIdx.z == 0) ? d0 : ((blockIdx.z == 1) ? d1 : d2);
    int m0 = blockIdx.y * 128;
    int n0 = blockIdx.x * 128;
    if (n0 >= d.Nc) return;

    int tid  = threadIdx.x;
    int lane = tid & 31;
    int w    = tid >> 5;
    int wm   = w >> 1;
    int wn   = w & 1;

    int a_r  = tid >> 2;
    int a_kq = (tid & 3) * 4;
    int b_k  = tid >> 5;
    int b_nq = (tid & 31) * 4;

    float4 aV[2], bV[2];
    float acc[2][8][4];
#pragma unroll
    for (int mf = 0; mf < 2; mf++)
#pragma unroll
        for (int nf = 0; nf < 8; nf++)
#pragma unroll
            for (int c = 0; c < 4; c++) acc[mf][nf][c] = 0.0f;

    auto loadA = [&](int k0) {
        const float* Ap = d.A; int lda = d.K1; int kk = k0;
        if (k0 >= d.K1) { Ap = d.A2; lda = d.K - d.K1; kk = k0 - d.K1; }
#pragma unroll
        for (int i = 0; i < 2; i++) {
            int pos = m0 + a_r + i * 64;
            aV[i] = *reinterpret_cast<const float4*>(&Ap[(size_t)pos * lda + kk + a_kq]);
        }
    };
    auto loadB = [&](int k0) {
        const float* Bp = d.B; int kk = k0;
        if (k0 >= d.K1) { Bp = d.B2; kk = k0 - d.K1; }
        int col = n0 + b_nq;
#pragma unroll
        for (int i = 0; i < 2; i++) {
            if (col < d.Nc) {
                bV[i] = *reinterpret_cast<const float4*>(&Bp[(size_t)(kk + b_k + i * 8) * d.Nc + col]);
            } else {
                bV[i] = make_float4(0.f, 0.f, 0.f, 0.f);
            }
        }
    };
    auto stsTile = [&](int buf) {
#pragma unroll
        for (int i = 0; i < 2; i++) {
            int r = a_r + i * 64;
            As[buf][r][a_kq + 0] = f2tf32(aV[i].x);
            As[buf][r][a_kq + 1] = f2tf32(aV[i].y);
            As[buf][r][a_kq + 2] = f2tf32(aV[i].z);
            As[buf][r][a_kq + 3] = f2tf32(aV[i].w);
        }
#pragma unroll
        for (int i = 0; i < 2; i++) {
            int kr = b_k + i * 8;
            Bs[buf][kr][b_nq + 0] = f2tf32(bV[i].x);
            Bs[buf][kr][b_nq + 1] = f2tf32(bV[i].y);
            Bs[buf][kr][b_nq + 2] = f2tf32(bV[i].z);
            Bs[buf][kr][b_nq + 3] = f2tf32(bV[i].w);
        }
    };

    loadA(0); loadB(0);
    stsTile(0);
    __syncthreads();

    int buf = 0;
    for (int k0 = 16; k0 <= d.K; k0 += 16) {
        bool nxt = (k0 < d.K);
        if (nxt) { loadA(k0); loadB(k0); }
#pragma unroll
        for (int s = 0; s < 2; s++) {
            uint32_t afr[2][4], bfr[8][2];
            int kk = s * 8 + (lane & 3);
#pragma unroll
            for (int mf = 0; mf < 2; mf++) {
                int rb = wm * 32 + mf * 16 + (lane >> 2);
                afr[mf][0] = As[buf][rb][kk];
                afr[mf][1] = As[buf][rb + 8][kk];
                afr[mf][2] = As[buf][rb][kk + 4];
                afr[mf][3] = As[buf][rb + 8][kk + 4];
            }
#pragma unroll
            for (int nf = 0; nf < 8; nf++) {
                int cb = wn * 64 + nf * 8 + (lane >> 2);
                bfr[nf][0] = Bs[buf][kk][cb];
                bfr[nf][1] = Bs[buf][kk + 4][cb];
            }
#pragma unroll
            for (int mf = 0; mf < 2; mf++)
#pragma unroll
                for (int nf = 0; nf < 8; nf++)
                    mma_tf32(acc[mf][nf], afr[mf], bfr[nf]);
        }
        if (nxt) stsTile(buf ^ 1);
        __syncthreads();
        buf ^= 1;
    }

#pragma unroll
    for (int mf = 0; mf < 2; mf++) {
#pragma unroll
        for (int r2 = 0; r2 < 2; r2++) {
            int crow = m0 + wm * 32 + mf * 16 + (lane >> 2) + r2 * 8;
#pragma unroll
            for (int nf = 0; nf < 8; nf++) {
#pragma unroll
                for (int c2 = 0; c2 < 2; c2++) {
                    int col = n0 + wn * 64 + nf * 8 + (lane & 3) * 2 + c2;
                    if (col >= d.Nc) continue;
                    size_t ci = (size_t)crow * d.Nc + col;
                    float val = acc[mf][nf][r2 * 2 + c2];
                    if (d.bias) val += d.bias[col];
                    if (d.flags & 2) val = val / (1.0f + expf(-val));
                    d.C[ci] = val;
                }
            }
        }
    }
}

// ---------------- MoE GEMM: grid.z = expert, gate/up split along x ----------------
__global__ __launch_bounds__(256, 2)
void moe_gemm_kernel(const float* __restrict__ A,
                     const float* __restrict__ Bg, const float* __restrict__ Bu,
                     size_t bStride, float* __restrict__ Cg, float* __restrict__ Cu,
                     const float* __restrict__ residual,
                     int Nc, int K, int xPart) {
    __shared__ uint32_t As[2][128][20];
    __shared__ uint32_t Bs[2][16][136];

    int e = blockIdx.z;
    int cnt = g_ecount[e];
    int m0 = blockIdx.y * 128;
    if (m0 >= cnt) return;
    int part = blockIdx.x / xPart;
    int n0 = (blockIdx.x % xPart) * 128;
    const float* B = (part ? Bu : Bg) + (size_t)e * bStride;
    float* C = part ? Cu : Cg;
    const int* gather = g_elist + e * PN;

    int tid  = threadIdx.x;
    int lane = tid & 31;
    int w    = tid >> 5;
    int wm   = w >> 1;
    int wn   = w & 1;

    int a_r  = tid >> 2;
    int a_kq = (tid & 3) * 4;
    int b_k  = tid >> 5;
    int b_nq = (tid & 31) * 4;

    float4 aV[2], bV[2];
    float acc[2][8][4];
#pragma unroll
    for (int mf = 0; mf < 2; mf++)
#pragma unroll
        for (int nf = 0; nf < 8; nf++)
#pragma unroll
            for (int c = 0; c < 4; c++) acc[mf][nf][c] = 0.0f;

    auto loadA = [&](int k0) {
#pragma unroll
        for (int i = 0; i < 2; i++) {
            int pos = m0 + a_r + i * 64;
            if (pos < cnt) {
                int ar = gather[pos];
                aV[i] = *reinterpret_cast<const float4*>(&A[(size_t)ar * K + k0 + a_kq]);
            } else {
                aV[i] = make_float4(0.f, 0.f, 0.f, 0.f);
            }
        }
    };
    auto loadB = [&](int k0) {
        int col = n0 + b_nq;
#pragma unroll
        for (int i = 0; i < 2; i++)
            bV[i] = *reinterpret_cast<const float4*>(&B[(size_t)(k0 + b_k + i * 8) * Nc + col]);
    };
    auto stsTile = [&](int buf) {
#pragma unroll
        for (int i = 0; i < 2; i++) {
            int r = a_r + i * 64;
            As[buf][r][a_kq + 0] = f2tf32(aV[i].x);
            As[buf][r][a_kq + 1] = f2tf32(aV[i].y);
            As[buf][r][a_kq + 2] = f2tf32(aV[i].z);
            As[buf][r][a_kq + 3] = f2tf32(aV[i].w);
        }
#pragma unroll
        for (int i = 0; i < 2; i++) {
            int kr = b_k + i * 8;
            Bs[buf][kr][b_nq + 0] = f2tf32(bV[i].x);
            Bs[buf][kr][b_nq + 1] = f2tf32(bV[i].y);
            Bs[buf][kr][b_nq + 2] = f2tf32(bV[i].z);
            Bs[buf][kr][b_nq + 3] = f2tf32(bV[i].w);
        }
    };

    loadA(0); loadB(0);
    stsTile(0);
    __syncthreads();

    int buf = 0;
    for (int k0 = 16; k0 <= K; k0 += 16) {
        bool nxt = (k0 < K);
        if (nxt) { loadA(k0); loadB(k0); }
#pragma unroll
        for (int s = 0; s < 2; s++) {
            uint32_t afr[2][4], bfr[8][2];
            int kk = s * 8 + (lane & 3);
#pragma unroll
            for (int mf = 0; mf < 2; mf++) {
                int rb = wm * 32 + mf * 16 + (lane >> 2);
                afr[mf][0] = As[buf][rb][kk];
                afr[mf][1] = As[buf][rb + 8][kk];
                afr[mf][2] = As[buf][rb][kk + 4];
                afr[mf][3] = As[buf][rb + 8][kk + 4];
            }
#pragma unroll
            for (int nf = 0; nf < 8; nf++) {
                int cb = wn * 64 + nf * 8 + (lane >> 2);
                bfr[nf][0] = Bs[buf][kk][cb];
                bfr[nf][1] = Bs[buf][kk + 4][cb];
            }
#pragma unroll
            for (int mf = 0; mf < 2; mf++)
#pragma unroll
                for (int nf = 0; nf < 8; nf++)
                    mma_tf32(acc[mf][nf], afr[mf], bfr[nf]);
        }
        if (nxt) stsTile(buf ^ 1);
        __syncthreads();
        buf ^= 1;
    }

#pragma unroll
    for (int mf = 0; mf < 2; mf++) {
#pragma unroll
        for (int r2 = 0; r2 < 2; r2++) {
            int pos = m0 + wm * 32 + mf * 16 + (lane >> 2) + r2 * 8;
            if (pos >= cnt) continue;
            int crow = gather[pos];
#pragma unroll
            for (int nf = 0; nf < 8; nf++) {
#pragma unroll
                for (int c2 = 0; c2 < 2; c2++) {
                    int col = n0 + wn * 64 + nf * 8 + (lane & 3) * 2 + c2;
                    size_t ci = (size_t)crow * Nc + col;
                    float val = acc[mf][nf][r2 * 2 + c2];
                    if (residual) val += residual[ci];
                    C[ci] = val;
                }
            }
        }
    }
}

// ---------------- per-head RMSNorm + RoPE ----------------
__global__ void qknorm_rope_kernel(float* __restrict__ x, const float* __restrict__ w,
                                   int heads, int nrows) {
    int row = blockIdx.x * 8 + (threadIdx.x >> 5);
    if (row >= nrows) return;
    int lane = threadIdx.x & 31;
    int n = row / heads;
    float* base = x + (size_t)row * PDH;
    float x1 = base[lane];
    float x2 = base[lane + 32];
    float s = x1 * x1 + x2 * x2;
#pragma unroll
    for (int off = 16; off > 0; off >>= 1) s += __shfl_xor_sync(0xffffffffu, s, off);
    float scale = rsqrtf(s / (float)PDH + P_EPS);
    x1 *= scale * w[lane];
    x2 *= scale * w[lane + 32];
    float c  = g_cosT[n * 32 + lane];
    float sn = g_sinT[n * 32 + lane];
    base[lane]      = x1 * c - x2 * sn;
    base[lane + 32] = x2 * c + x1 * sn;
}

// ---------------- tensor-core flash attention ----------------
// 128 queries/block, 32-key tiles, 8 warps (each owns 16 full rows -> warp-local softmax).
// Q in register fragments; K/V/P in smem with conflict-free pads.
__global__ __launch_bounds__(256, 1)
void attn_tc_kernel(const float* __restrict__ q, const float* __restrict__ k,
                    const float* __restrict__ v, float* __restrict__ o) {
    __shared__ uint32_t Ks[32][68];   // [kv][d]  bank: 4*(l>>2)+(l&3)  conflict-free
    __shared__ uint32_t Vs[32][72];   // [kv][d]  bank: 8*(l&3)+(l>>2)  conflict-free
    __shared__ uint32_t Ps[128][36];  // [row][kv] A-frag bank: 4*(l>>2)+(l&3) conflict-free

    int qb = blockIdx.x, h = blockIdx.y;
    int kvh = h >> 2;                 // H/KV = 4
    int q0 = qb * 128;
    int tid = threadIdx.x;
    int lane = tid & 31;
    int w = tid >> 5;
    int lr = lane >> 2, lc = lane & 3;

    // Q fragments in registers: rows w*16 + lr (+8), all 8 k-steps over DH=64
    uint32_t qfr[8][4];
    {
        const float* qb_ = q + (size_t)(q0 + w * 16) * PD + h * PDH;
#pragma unroll
        for (int ks = 0; ks < 8; ks++) {
            int c = ks * 8 + lc;
            qfr[ks][0] = f2tf32(qb_[(size_t)lr * PD + c]);
            qfr[ks][1] = f2tf32(qb_[(size_t)(lr + 8) * PD + c]);
            qfr[ks][2] = f2tf32(qb_[(size_t)lr * PD + c + 4]);
            qfr[ks][3] = f2tf32(qb_[(size_t)(lr + 8) * PD + c + 4]);
        }
    }

    float accO[8][4];
#pragma unroll
    for (int nf = 0; nf < 8; nf++)
#pragma unroll
        for (int c = 0; c < 4; c++) accO[nf][c] = 0.0f;
    float m0 = -INFINITY, m1 = -INFINITY, l0 = 0.0f, l1 = 0.0f;
    const float scale = 0.125f;

    for (int t = 0; t < PN / 32; t++) {
        // load K/V tile (32x64 each), cvt to tf32, STS.128
#pragma unroll
        for (int it = 0; it < 2; it++) {
            int i = tid + it * 256;
            int kv = i >> 4, d4 = (i & 15) * 4;
            size_t gi = (size_t)(t * 32 + kv) * (PKV * PDH) + kvh * PDH + d4;
            float4 kf = *reinterpret_cast<const float4*>(&k[gi]);
            float4 vf = *reinterpret_cast<const float4*>(&v[gi]);
            uint4 kt = make_uint4(f2tf32(kf.x), f2tf32(kf.y), f2tf32(kf.z), f2tf32(kf.w));
            uint4 vt = make_uint4(f2tf32(vf.x), f2tf32(vf.y), f2tf32(vf.z), f2tf32(vf.w));
            *reinterpret_cast<uint4*>(&Ks[kv][d4]) = kt;
            *reinterpret_cast<uint4*>(&Vs[kv][d4]) = vt;
        }
        __syncthreads();

        // S = Q K^T : warp tile 16 x 32 (4 n-blocks)
        float sacc[4][4];
#pragma unroll
        for (int nf = 0; nf < 4; nf++)
#pragma unroll
            for (int c = 0; c < 4; c++) sacc[nf][c] = 0.0f;
#pragma unroll
        for (int ks = 0; ks < 8; ks++) {
#pragma unroll
            for (int nf = 0; nf < 4; nf++) {
                uint32_t b[2];
                b[0] = Ks[nf * 8 + lr][ks * 8 + lc];
                b[1] = Ks[nf * 8 + lr][ks * 8 + lc + 4];
                mma_tf32(sacc[nf], qfr[ks], b);
            }
        }

        // warp-local online softmax (rows w*16+lr and +8)
        float mloc0 = -INFINITY, mloc1 = -INFINITY;
#pragma unroll
        for (int nf = 0; nf < 4; nf++) {
#pragma unroll
            for (int c = 0; c < 4; c++) sacc[nf][c] *= scale;
            mloc0 = fmaxf(mloc0, fmaxf(sacc[nf][0], sacc[nf][1]));
            mloc1 = fmaxf(mloc1, fmaxf(sacc[nf][2], sacc[nf][3]));
        }
        mloc0 = fmaxf(mloc0, __shfl_xor_sync(0xffffffffu, mloc0, 1));
        mloc0 = fmaxf(mloc0, __shfl_xor_sync(0xffffffffu, mloc0, 2));
        mloc1 = fmaxf(mloc1, __shfl_xor_sync(0xffffffffu, mloc1, 1));
        mloc1 = fmaxf(mloc1, __shfl_xor_sync(0xffffffffu, mloc1, 2));
        float mn0 = fmaxf(m0, mloc0), mn1 = fmaxf(m1, mloc1);
        float corr0 = __expf(m0 - mn0), corr1 = __expf(m1 - mn1);
        float ls0 = 0.0f, ls1 = 0.0f;
        int prow = w * 16 + lr;
#pragma unroll
        for (int nf = 0; nf < 4; nf++) {
            float p00 = __expf(sacc[nf][0] - mn0);
            float p01 = __expf(sacc[nf][1] - mn0);
            float p10 = __expf(sacc[nf][2] - mn1);
            float p11 = __expf(sacc[nf][3] - mn1);
            ls0 += p00 + p01;
            ls1 += p10 + p11;
            int col = nf * 8 + 2 * lc;
            *reinterpret_cast<uint2*>(&Ps[prow][col])     = make_uint2(f2tf32(p00), f2tf32(p01));
            *reinterpret_cast<uint2*>(&Ps[prow + 8][col]) = make_uint2(f2tf32(p10), f2tf32(p11));
        }
        ls0 += __shfl_xor_sync(0xffffffffu, ls0, 1);
        ls0 += __shfl_xor_sync(0xffffffffu, ls0, 2);
        ls1 += __shfl_xor_sync(0xffffffffu, ls1, 1);
        ls1 += __shfl_xor_sync(0xffffffffu, ls1, 2);
        l0 = l0 * corr0 + ls0;
        l1 = l1 * corr1 + ls1;
        m0 = mn0; m1 = mn1;
#pragma unroll
        for (int nf = 0; nf < 8; nf++) {
            accO[nf][0] *= corr0; accO[nf][1] *= corr0;
            accO[nf][2] *= corr1; accO[nf][3] *= corr1;
        }
        __syncthreads();

        // O += P V : k over 32 kv (4 k-steps), 8 d-blocks
#pragma unroll
        for (int ks2 = 0; ks2 < 4; ks2++) {
            uint32_t a[4];
            a[0] = Ps[w * 16 + lr][ks2 * 8 + lc];
            a[1] = Ps[w * 16 + lr + 8][ks2 * 8 + lc];
            a[2] = Ps[w * 16 + lr][ks2 * 8 + lc + 4];
            a[3] = Ps[w * 16 + lr + 8][ks2 * 8 + lc + 4];
#pragma unroll
            for (int nf = 0; nf < 8; nf++) {
                uint32_t b[2];
                b[0] = Vs[ks2 * 8 + lc][nf * 8 + lr];
                b[1] = Vs[ks2 * 8 + lc + 4][nf * 8 + lr];
                mma_tf32(accO[nf], a, b);
            }
        }
        __syncthreads();
    }

    // epilogue
    float il0 = 1.0f / l0, il1 = 1.0f / l1;
    int row0 = q0 + w * 16 + lr;
#pragma unroll
    for (int nf = 0; nf < 8; nf++) {
        int col = h * PDH + nf * 8 + 2 * lc;
        *reinterpret_cast<float2*>(&o[(size_t)row0 * PD + col]) =
            make_float2(accO[nf][0] * il0, accO[nf][1] * il0);
        *reinterpret_cast<float2*>(&o[(size_t)(row0 + 8) * PD + col]) =
            make_float2(accO[nf][2] * il1, accO[nf][3] * il1);
    }
}

// ---------------- fused state-update ----------------
__global__ void fuse1_kernel(const float* __restrict__ co, const float* __restrict__ velocity,
                             const float* __restrict__ o, const float* __restrict__ mu_cur,
                             const float* __restrict__ hidden_in,
                             float* __restrict__ out_vnext, float* __restrict__ hidmid) {
    size_t i = (size_t)blockIdx.x * blockDim.x + threadIdx.x;
    if (i >= (size_t)PN * PD) return;
    int n = (int)(i / PD), d = (int)(i % PD);
    const float* cor = co + (size_t)n * 3 * PD;
    float alpha = sigmoidf_(cor[d]);
    float beta  = fminf(softplusf_(cor[PD + d]), 2.0f);
    float gate  = sigmoidf_(cor[2 * PD + d]);
    float ov = o[i], mc = mu_cur[i], vel = velocity[i];
    float err = ov - mc;
    float vn = alpha * vel - beta * err;
    vn = fminf(fmaxf(vn, -10.0f), 10.0f);
    out_vnext[i] = vn;
    hidmid[i] = hidden_in[i] + ov + P_DT * gate * vn;
}

// ---------------- router ----------------
__global__ void router_kernel(const float* __restrict__ mu_cur, const float* __restrict__ w,
                              const int* __restrict__ token_ids) {
    int tkn = blockIdx.x * 8 + (threadIdx.x >> 5);
    if (tkn >= PN) return;
    int lane = threadIdx.x & 31;
    float lg[PE];
#pragma unroll
    for (int e = 0; e < PE; e++) lg[e] = 0.0f;
    const float* xr = mu_cur + (size_t)tkn * PD;
    for (int d = lane; d < PD; d += 32) {
        float xv = xr[d];
        const float* wr = w + (size_t)d * PE;
#pragma unroll
        for (int e = 0; e < PE; e++) lg[e] += xv * wr[e];
    }
#pragma unroll
    for (int e = 0; e < PE; e++) {
#pragma unroll
        for (int off = 16; off > 0; off >>= 1)
            lg[e] += __shfl_xor_sync(0xffffffffu, lg[e], off);
    }
    if (lane == 0) {
        int b = token_ids[tkn] % PE;
        lg[b] += P_BASE_SCALE;
        int best = 0; float bv = lg[0];
#pragma unroll
        for (int e = 1; e < PE; e++) {
            if (lg[e] > bv) { bv = lg[e]; best = e; }
        }
        int slot = atomicAdd(&g_ecount[best], 1);
        g_elist[best * PN + slot] = tkn;
    }
}

__global__ void midcombine_kernel() {
    size_t i = (size_t)blockIdx.x * blockDim.x + threadIdx.x;
    if (i >= (size_t)PN * PF) return;
    float gv = g_G[i];
    g_mid[i] = (gv / (1.0f + expf(-gv))) * g_U[i];
}

// ---------------- host launch ----------------
static inline void* sym_addr(const void* sym) {
    void* p = nullptr;
    cudaGetSymbolAddress(&p, sym);
    return p;
}

extern "C" void kernel_launch(void* const* d_in, const int* in_sizes, int n_in,
                              void* d_out, int out_size) {
    const float* hidden    = (const float*)d_in[0];
    const int*   positions = (const int*)d_in[1];
    const float* velocity  = (const float*)d_in[2];
    const int*   token_ids = (const int*)d_in[3];
    const float* mu_prev   = (const float*)d_in[4];
    const float* ln1_w     = (const float*)d_in[5];
    const float* ln2_w     = (const float*)d_in[6];
    const float* wq        = (const float*)d_in[7];
    const float* wk        = (const float*)d_in[8];
    const float* wv        = (const float*)d_in[9];
    const float* wo        = (const float*)d_in[10];
    const float* w_mu_q    = (const float*)d_in[11];
    const float* w_mu_k    = (const float*)d_in[12];
    const float* w_mu_v    = (const float*)d_in[13];
    const float* qnorm_w   = (const float*)d_in[14];
    const float* knorm_w   = (const float*)d_in[15];
    const float* dyn_mu    = (const float*)d_in[16];
    const float* dyn_proj  = (const float*)d_in[17];
    const float* ctrl_in_w = (const float*)d_in[18];
    const float* ctrl_in_b = (const float*)d_in[19];
    const float* ctrl_out_w= (const float*)d_in[20];
    const float* ctrl_out_b= (const float*)d_in[21];
    const float* mu_router = (const float*)d_in[22];
    const float* w_gate    = (const float*)d_in[23];
    const float* w_up      = (const float*)d_in[24];
    const float* w_down    = (const float*)d_in[25];

    float* out_hidden = (float*)d_out;
    float* out_vnext  = out_hidden + (size_t)PN * PD;
    float* out_mucur  = out_vnext  + (size_t)PN * PD;

    float* p_hnorm  = (float*)sym_addr(g_hnorm);
    float* p_q      = (float*)sym_addr(g_q);
    float* p_k      = (float*)sym_addr(g_k);
    float* p_v      = (float*)sym_addr(g_v);
    float* p_attno  = (float*)sym_addr(g_attno);
    float* p_o      = (float*)sym_addr(g_o);
    float* p_ctrl   = (float*)sym_addr(g_ctrl);
    float* p_co     = (float*)sym_addr(g_co);
    float* p_hidmid = (float*)sym_addr(g_hidmid);
    float* p_xnorm  = (float*)sym_addr(g_xnorm);
    float* p_G      = (float*)sym_addr(g_G);
    float* p_U      = (float*)sym_addr(g_U);
    float* p_mid    = (float*)sym_addr(g_mid);

    zero_counts_kernel<<<1, 32>>>();
    rope_table_kernel<<<(PN * 32 + 255) / 256, 256>>>(positions);
    rmsnorm_kernel<<<PN, 256>>>(hidden, ln1_w, p_hnorm);

    // QKV in ONE launch
    {
        GDesc dq { p_hnorm, mu_prev, wq, w_mu_q, nullptr, p_q, PH * PDH, 2 * PD, PD, 0 };
        GDesc dk { p_hnorm, mu_prev, wk, w_mu_k, nullptr, p_k, PKV * PDH, 2 * PD, PD, 0 };
        GDesc dv { p_hnorm, mu_prev, wv, w_mu_v, nullptr, p_v, PKV * PDH, 2 * PD, PD, 0 };
        tf32_gemm_multi<<<dim3(8, 16, 3), 256>>>(dq, dk, dv);
    }

    qknorm_rope_kernel<<<(PN * PH + 7) / 8, 256>>>(p_q, qnorm_w, PH, PN * PH);
    qknorm_rope_kernel<<<(PN * PKV + 7) / 8, 256>>>(p_k, knorm_w, PKV, PN * PKV);

    // tensor-core attention
    attn_tc_kernel<<<dim3(PN / 128, PH), 256>>>(p_q, p_k, p_v, p_attno);

    // o = attno @ wo
    {
        GDesc d { p_attno, nullptr, wo, nullptr, nullptr, p_o, PD, PD, PD, 0 };
        tf32_gemm_multi<<<dim3(8, 16, 1), 256>>>(d, d, d);
    }

    // dyn-proj and ctrl concurrently
    {
        GDesc dd { p_o, nullptr, dyn_proj, nullptr, dyn_mu, out_mucur, PD, PD, PD, 0 };
        GDesc dc { p_o, velocity, ctrl_in_w, ctrl_in_w + PD * PCH, ctrl_in_b, p_ctrl,
                   PCH, 2 * PD, PD, 2 };
        tf32_gemm_multi<<<dim3(8, 16, 2), 256>>>(dd, dc, dc);
    }

    // co = ctrl @ ctrl_out_w + ctrl_out_b
    {
        GDesc d { p_ctrl, nullptr, ctrl_out_w, nullptr, ctrl_out_b, p_co, 3 * PD, PCH, PCH, 0 };
        tf32_gemm_multi<<<dim3(24, 16, 1), 256>>>(d, d, d);
    }

    fuse1_kernel<<<(PN * PD + 255) / 256, 256>>>(p_co, velocity, p_o, out_mucur, hidden,
                                                 out_vnext, p_hidmid);

    rmsnorm_kernel<<<PN, 256>>>(p_hidmid, ln2_w, p_xnorm);
    router_kernel<<<(PN + 7) / 8, 256>>>(out_mucur, mu_router, token_ids);

    moe_gemm_kernel<<<dim3(32, 16, PE), 256>>>(p_xnorm, w_gate, w_up,
                                               (size_t)PD * PF, p_G, p_U,
                                               nullptr, PF, PD, 16);
    midcombine_kernel<<<(PN * PF + 255) / 256, 256>>>();

    moe_gemm_kernel<<<dim3(8, 16, PE), 256>>>(p_mid, w_down, nullptr,
                                              (size_t)PF * PD, out_hidden, nullptr,
                                              p_hidmid, PD, PF, 8);
}